// round 4
// baseline (speedup 1.0000x reference)
#include <cuda_runtime.h>
#include <math.h>

#define BATCH  8
#define CINCH  256
#define HIDCH  256
#define NHEADS 8
#define HDIM   32
#define KSZ    31
#define PADW   15
#define WIDTH  16384

// ---- scratch (device globals; no allocation allowed) ----
__device__ float g_qWk[CINCH * NHEADS];                 // [D][h]
__device__ float g_qb[NHEADS];
__device__ float g_costE[BATCH * NHEADS * WIDTH];       // 4 MB
__device__ float g_rinv [BATCH * NHEADS * WIDTH];       // 4 MB  (1 / denom conv)
__device__ float g_vc[BATCH * HIDCH * WIDTH];           // 128 MB
__device__ float g_r [BATCH * HIDCH * WIDTH];           // 128 MB

// ---- packed f32x2 helpers (sm_103a FFMA2 path) ----
__device__ __forceinline__ void fma2(unsigned long long& d,
                                     unsigned long long a,
                                     unsigned long long b) {
    asm("fma.rn.f32x2 %0, %1, %2, %0;" : "+l"(d) : "l"(a), "l"(b));
}
__device__ __forceinline__ unsigned long long pack2(float v) {
    unsigned long long r;
    asm("mov.b64 %0, {%1, %1};" : "=l"(r) : "f"(v));
    return r;
}
__device__ __forceinline__ float2 unpack2(unsigned long long v) {
    float2 f;
    asm("mov.b64 {%0, %1}, %2;" : "=f"(f.x), "=f"(f.y) : "l"(v));
    return f;
}

// ============================================================
// Kernel 0: precompute qWk[D][h], qb[h]  (batch-independent)
// ============================================================
__global__ void precompute_kernel(const float* __restrict__ query,
                                  const float* __restrict__ Wk,
                                  const float* __restrict__ Wkb) {
    __shared__ float sq[CINCH];
    __shared__ float qn[CINCH];
    __shared__ float nrm[NHEADS];
    int tid = threadIdx.x;   // 0..255
    float qv = query[tid];
    sq[tid] = qv * qv;
    __syncthreads();
    if (tid < NHEADS) {
        float s = 0.f;
        #pragma unroll
        for (int d = 0; d < HDIM; d++) s += sq[tid * HDIM + d];
        nrm[tid] = sqrtf(s) + 1e-6f;
    }
    __syncthreads();
    qn[tid] = qv / nrm[tid / HDIM] * 0.17677669529663687f;   // /(norm+eps)/sqrt(HD)
    __syncthreads();
    int D = tid;
    #pragma unroll
    for (int h = 0; h < NHEADS; h++) {
        float s = 0.f;
        const float* wrow = Wk + D * HIDCH + h * HDIM;
        #pragma unroll
        for (int d = 0; d < HDIM; d++) s += qn[h * HDIM + d] * wrow[d];
        g_qWk[D * NHEADS + h] = s;
    }
    if (tid < NHEADS) {
        float s = 0.f;
        #pragma unroll
        for (int d = 0; d < HDIM; d++) s += Wkb[tid * HDIM + d] * qn[tid * HDIM + d];
        g_qb[tid] = s;
    }
}

// ============================================================
// Kernel 1: cost_exp[b][h][w] = exp( sum_D x[b][D][w]*qWk[D][h] + qb[h] )
// ============================================================
__global__ void __launch_bounds__(256) cost_kernel(const float* __restrict__ x) {
    __shared__ float sW[CINCH * NHEADS];
    __shared__ float sb[NHEADS];
    int tid = threadIdx.x;
    for (int i = tid; i < CINCH * NHEADS; i += 256) sW[i] = g_qWk[i];
    if (tid < NHEADS) sb[tid] = g_qb[tid];
    __syncthreads();

    int b = blockIdx.y;
    int w = blockIdx.x * 256 + tid;
    const float* xb = x + (size_t)b * CINCH * WIDTH + w;

    float acc[NHEADS];
    #pragma unroll
    for (int h = 0; h < NHEADS; h++) acc[h] = sb[h];

    for (int D = 0; D < CINCH; D++) {
        float v = __ldg(xb + (size_t)D * WIDTH);
        #pragma unroll
        for (int h = 0; h < NHEADS; h++) acc[h] = fmaf(v, sW[D * NHEADS + h], acc[h]);
    }
    #pragma unroll
    for (int h = 0; h < NHEADS; h++)
        g_costE[((size_t)b * NHEADS + h) * WIDTH + w] = expf(acc[h]);
}

// ============================================================
// Kernel 2: denominator conv (per b,h row):
//   rinv[b][h][w] = 1 / sum_k cE[b][h][w-15+k] * rpeE[h][k]
// ============================================================
__global__ void __launch_bounds__(256) denom_kernel(const float* __restrict__ rpe) {
    __shared__ float s[256 + 32];
    __shared__ float rks[KSZ];
    int h = blockIdx.y;
    int b = blockIdx.z;
    int w0 = blockIdx.x * 256;
    int tid = threadIdx.x;
    if (tid < KSZ) rks[tid] = expf(rpe[h * KSZ + tid]);
    const float* crow = g_costE + ((size_t)b * NHEADS + h) * WIDTH;
    #pragma unroll
    for (int i = tid; i < 256 + 32; i += 256) {
        int g = w0 - PADW + i;
        s[i] = (g >= 0 && g < WIDTH) ? crow[g] : 0.f;
    }
    __syncthreads();
    float rkr[KSZ];
    #pragma unroll
    for (int k = 0; k < KSZ; k++) rkr[k] = rks[k];
    float sc = 0.f;
    #pragma unroll
    for (int k = 0; k < KSZ; k++) sc = fmaf(s[tid + k], rkr[k], sc);
    g_rinv[((size_t)b * NHEADS + h) * WIDTH + w0 + tid] = 1.0f / sc;
}

// ============================================================
// Kernel 3: 31-tap depthwise conv on vc, times precomputed 1/denom.
//   Per block: one (b,c), 1024 outputs, ILP=4 per thread.
// ============================================================
#define CTILE 1024
__global__ void __launch_bounds__(256) conv_kernel(const float* __restrict__ rpe) {
    __shared__ __align__(16) float s[CTILE + 36];
    __shared__ float rks[KSZ];
    int c = blockIdx.y;
    int h = c >> 5;
    int b = blockIdx.z;
    int w0 = blockIdx.x * CTILE;
    int tid = threadIdx.x;
    if (tid < KSZ) rks[tid] = expf(rpe[h * KSZ + tid]);

    const float* vrow = g_vc + ((size_t)b * HIDCH + c) * WIDTH;
    // zero-padded tile load: s[i] = vrow[w0 - 15 + i]
    #pragma unroll
    for (int i = tid; i < CTILE + 36; i += 256) {
        int g = w0 - PADW + i;
        s[i] = (g >= 0 && g < WIDTH) ? __ldg(vrow + g) : 0.f;
    }
    __syncthreads();

    float rkr[KSZ];
    #pragma unroll
    for (int k = 0; k < KSZ; k++) rkr[k] = rks[k];

    const int t4 = tid * 4;
    float a0 = 0.f, a1 = 0.f, a2 = 0.f, a3 = 0.f;
    #pragma unroll
    for (int u = 0; u < 9; u++) {
        float4 v4 = *(const float4*)&s[t4 + u * 4];
        float vv[4] = {v4.x, v4.y, v4.z, v4.w};
        #pragma unroll
        for (int e = 0; e < 4; e++) {
            const int m = u * 4 + e;
            if (m >= 0 && m < KSZ)         a0 = fmaf(vv[e], rkr[m],     a0);
            if (m - 1 >= 0 && m - 1 < KSZ) a1 = fmaf(vv[e], rkr[m - 1], a1);
            if (m - 2 >= 0 && m - 2 < KSZ) a2 = fmaf(vv[e], rkr[m - 2], a2);
            if (m - 3 >= 0 && m - 3 < KSZ) a3 = fmaf(vv[e], rkr[m - 3], a3);
        }
    }
    const float* rinv = g_rinv + ((size_t)b * NHEADS + h) * WIDTH + w0 + t4;
    float4 ri = *(const float4*)rinv;
    float4 o;
    o.x = a0 * ri.x;
    o.y = a1 * ri.y;
    o.z = a2 * ri.z;
    o.w = a3 * ri.w;
    *(float4*)&g_r[((size_t)b * HIDCH + c) * WIDTH + w0 + t4] = o;
}

// ============================================================
// SGEMM: C[c][w] = sum_d Wt[c][d] * X[d][w]  (+ epilogue)
//   MODE 0: X = x (batch slice), Out = g_vc, scaled by cost_exp
//   MODE 1: X = g_r (batch slice), Out = out param, plain bias
//   Inner loop uses packed fma.rn.f32x2 (FFMA2): acc pairs along c-rows.
// ============================================================
#define BM 128
#define BN 128
#define BK 16

template <int MODE>
__global__ void __launch_bounds__(256) gemm_kernel(const float* __restrict__ Wt,
                                                   const float* __restrict__ Xglobal,
                                                   const float* __restrict__ bias,
                                                   float* __restrict__ OutGlobal) {
    __shared__ __align__(16) float As[BK][BM];   // weight tile, transposed
    __shared__ __align__(16) float Bs[BK][BN];

    const int bn = blockIdx.x * BN;
    const int bm = blockIdx.y * BM;
    const int b  = blockIdx.z;

    const float* Xb = (MODE == 0)
        ? (Xglobal + (size_t)b * CINCH * WIDTH)
        : (g_r + (size_t)b * HIDCH * WIDTH);

    const int tid = threadIdx.x;
    const int tx = tid & 15;   // 0..15 (w dir)
    const int ty = tid >> 4;   // 0..15 (c dir)

    // acc2[ip][j] = packed {acc[2ip][j], acc[2ip+1][j]}
    unsigned long long acc2[4][8];
    #pragma unroll
    for (int i = 0; i < 4; i++)
        #pragma unroll
        for (int j = 0; j < 8; j++) acc2[i][j] = 0ULL;

    for (int k0 = 0; k0 < CINCH; k0 += BK) {
        #pragma unroll
        for (int v = 0; v < 2; v++) {
            int u  = tid * 2 + v;
            int r  = u >> 2;
            int c4 = u & 3;
            float4 a4 = *(const float4*)(Wt + (size_t)(bm + r) * CINCH + k0 + c4 * 4);
            As[c4 * 4 + 0][r] = a4.x;
            As[c4 * 4 + 1][r] = a4.y;
            As[c4 * 4 + 2][r] = a4.z;
            As[c4 * 4 + 3][r] = a4.w;
        }
        #pragma unroll
        for (int v = 0; v < 2; v++) {
            int u  = tid * 2 + v;
            int r  = u >> 5;
            int c4 = u & 31;
            *(float4*)&Bs[r][c4 * 4] =
                *(const float4*)(Xb + (size_t)(k0 + r) * WIDTH + bn + c4 * 4);
        }
        __syncthreads();

        #pragma unroll
        for (int kk = 0; kk < BK; kk++) {
            // A fragment: 8 consecutive floats -> 4 packed f32x2, loaded directly
            ulonglong2 aA = *(const ulonglong2*)&As[kk][ty * 8];
            ulonglong2 aB = *(const ulonglong2*)&As[kk][ty * 8 + 4];
            unsigned long long a2[4] = {aA.x, aA.y, aB.x, aB.y};
            // B fragment: 8 floats, duplicated into both halves
            float4 b0 = *(const float4*)&Bs[kk][tx * 8];
            float4 b1 = *(const float4*)&Bs[kk][tx * 8 + 4];
            unsigned long long bd[8];
            bd[0] = pack2(b0.x); bd[1] = pack2(b0.y);
            bd[2] = pack2(b0.z); bd[3] = pack2(b0.w);
            bd[4] = pack2(b1.x); bd[5] = pack2(b1.y);
            bd[6] = pack2(b1.z); bd[7] = pack2(b1.w);
            #pragma unroll
            for (int ip = 0; ip < 4; ip++)
                #pragma unroll
                for (int j = 0; j < 8; j++)
                    fma2(acc2[ip][j], a2[ip], bd[j]);
        }
        __syncthreads();
    }

    // epilogue: unpack row pairs
    #pragma unroll
    for (int ip = 0; ip < 4; ip++) {
        float r0[8], r1[8];
        #pragma unroll
        for (int j = 0; j < 8; j++) {
            float2 p = unpack2(acc2[ip][j]);
            r0[j] = p.x;   // row i = 2*ip
            r1[j] = p.y;   // row i = 2*ip + 1
        }
        #pragma unroll
        for (int half = 0; half < 2; half++) {
            float* rr = half ? r1 : r0;
            int c = bm + ty * 8 + ip * 2 + half;
            float bv = bias[c];
            size_t obase = ((size_t)b * HIDCH + c) * WIDTH + bn + tx * 8;
            if (MODE == 0) {
                const float* ce = g_costE + ((size_t)b * NHEADS + (c >> 5)) * WIDTH + bn + tx * 8;
                float o[8];
                #pragma unroll
                for (int j = 0; j < 8; j++) o[j] = ce[j] * (rr[j] + bv);
                *(float4*)&g_vc[obase]     = *(float4*)&o[0];
                *(float4*)&g_vc[obase + 4] = *(float4*)&o[4];
            } else {
                float o[8];
                #pragma unroll
                for (int j = 0; j < 8; j++) o[j] = rr[j] + bv;
                *(float4*)&OutGlobal[obase]     = *(float4*)&o[0];
                *(float4*)&OutGlobal[obase + 4] = *(float4*)&o[4];
            }
        }
    }
}

// ============================================================
extern "C" void kernel_launch(void* const* d_in, const int* in_sizes, int n_in,
                              void* d_out, int out_size) {
    const float* x     = (const float*)d_in[0];
    const float* query = (const float*)d_in[1];
    const float* Wk    = (const float*)d_in[2];
    const float* Wkb   = (const float*)d_in[3];
    const float* rpe   = (const float*)d_in[4];
    const float* Wv    = (const float*)d_in[5];
    const float* bv    = (const float*)d_in[6];
    const float* Wo    = (const float*)d_in[7];
    const float* bo    = (const float*)d_in[8];
    float* out = (float*)d_out;

    precompute_kernel<<<1, 256>>>(query, Wk, Wkb);
    cost_kernel<<<dim3(WIDTH / 256, BATCH), 256>>>(x);
    denom_kernel<<<dim3(WIDTH / 256, NHEADS, BATCH), 256>>>(rpe);
    gemm_kernel<0><<<dim3(WIDTH / BN, HIDCH / BM, BATCH), 256>>>(Wv, x, bv, nullptr);
    conv_kernel<<<dim3(WIDTH / CTILE, HIDCH, BATCH), 256>>>(rpe);
    gemm_kernel<1><<<dim3(WIDTH / BN, HIDCH / BM, BATCH), 256>>>(Wo, nullptr, bo, out);
}

// round 6
// speedup vs baseline: 1.6222x; 1.6222x over previous
#include <cuda_runtime.h>
#include <cuda_bf16.h>
#include <cstdint>
#include <math.h>

#define BATCH  8
#define CINCH  256
#define HIDCH  256
#define NHEADS 8
#define HDIM   32
#define KSZ    31
#define PADW   15
#define WIDTH  16384

// ---- scratch (device globals; no allocation allowed) ----
__device__ float g_qWk[CINCH * NHEADS];
__device__ float g_qb[NHEADS];
__device__ float g_costE[BATCH * NHEADS * WIDTH];       // 4 MB
__device__ float g_rinv [BATCH * NHEADS * WIDTH];       // 4 MB
__device__ float g_vc[(size_t)BATCH * HIDCH * WIDTH];   // 128 MB
__device__ float g_r [(size_t)BATCH * HIDCH * WIDTH];   // 128 MB

// ============================================================
// helpers
// ============================================================
__device__ __forceinline__ uint32_t smem_to_u32(const void* p) {
    uint32_t a;
    asm("{ .reg .u64 t; cvta.to.shared.u64 t, %1; cvt.u32.u64 %0, t; }" : "=r"(a) : "l"(p));
    return a;
}
__device__ __forceinline__ void ldsm_x4(uint32_t* r, uint32_t addr) {
    asm volatile("ldmatrix.sync.aligned.m8n8.x4.shared.b16 {%0,%1,%2,%3}, [%4];"
                 : "=r"(r[0]), "=r"(r[1]), "=r"(r[2]), "=r"(r[3]) : "r"(addr));
}
__device__ __forceinline__ void ldsm_x2t(uint32_t* r, uint32_t addr) {
    asm volatile("ldmatrix.sync.aligned.m8n8.x2.trans.shared.b16 {%0,%1}, [%2];"
                 : "=r"(r[0]), "=r"(r[1]) : "r"(addr));
}
__device__ __forceinline__ void mma_bf16(float* d, const uint32_t* a, const uint32_t* b) {
    asm volatile("mma.sync.aligned.m16n8k16.row.col.f32.bf16.bf16.f32 "
                 "{%0,%1,%2,%3}, {%4,%5,%6,%7}, {%8,%9}, {%0,%1,%2,%3};"
                 : "+f"(d[0]), "+f"(d[1]), "+f"(d[2]), "+f"(d[3])
                 : "r"(a[0]), "r"(a[1]), "r"(a[2]), "r"(a[3]),
                   "r"(b[0]), "r"(b[1]));
}
// split one float into (hi, lo) bf16 pair bits
__device__ __forceinline__ void split_bf16(float v, uint16_t& hi, uint16_t& lo) {
    __nv_bfloat16 h = __float2bfloat16_rn(v);
    float r = v - __bfloat162float(h);
    __nv_bfloat16 l = __float2bfloat16_rn(r);
    hi = *(uint16_t*)&h;
    lo = *(uint16_t*)&l;
}

// ============================================================
// Kernel 0: precompute qWk[D][h], qb[h]
// ============================================================
__global__ void precompute_kernel(const float* __restrict__ query,
                                  const float* __restrict__ Wk,
                                  const float* __restrict__ Wkb) {
    __shared__ float sq[CINCH];
    __shared__ float qn[CINCH];
    __shared__ float nrm[NHEADS];
    int tid = threadIdx.x;
    float qv = query[tid];
    sq[tid] = qv * qv;
    __syncthreads();
    if (tid < NHEADS) {
        float s = 0.f;
        #pragma unroll
        for (int d = 0; d < HDIM; d++) s += sq[tid * HDIM + d];
        nrm[tid] = sqrtf(s) + 1e-6f;
    }
    __syncthreads();
    qn[tid] = qv / nrm[tid / HDIM] * 0.17677669529663687f;
    __syncthreads();
    int D = tid;
    #pragma unroll
    for (int h = 0; h < NHEADS; h++) {
        float s = 0.f;
        const float* wrow = Wk + D * HIDCH + h * HDIM;
        #pragma unroll
        for (int d = 0; d < HDIM; d++) s += qn[h * HDIM + d] * wrow[d];
        g_qWk[D * NHEADS + h] = s;
    }
    if (tid < NHEADS) {
        float s = 0.f;
        #pragma unroll
        for (int d = 0; d < HDIM; d++) s += Wkb[tid * HDIM + d] * qn[tid * HDIM + d];
        g_qb[tid] = s;
    }
}

// ============================================================
// Kernel 1: cost_exp[b][h][w]
// ============================================================
__global__ void __launch_bounds__(256) cost_kernel(const float* __restrict__ x) {
    __shared__ float sW[CINCH * NHEADS];
    __shared__ float sb[NHEADS];
    int tid = threadIdx.x;
    for (int i = tid; i < CINCH * NHEADS; i += 256) sW[i] = g_qWk[i];
    if (tid < NHEADS) sb[tid] = g_qb[tid];
    __syncthreads();

    int b = blockIdx.y;
    int w = blockIdx.x * 256 + tid;
    const float* xb = x + (size_t)b * CINCH * WIDTH + w;

    float acc[NHEADS];
    #pragma unroll
    for (int h = 0; h < NHEADS; h++) acc[h] = sb[h];

    for (int D = 0; D < CINCH; D++) {
        float v = __ldg(xb + (size_t)D * WIDTH);
        #pragma unroll
        for (int h = 0; h < NHEADS; h++) acc[h] = fmaf(v, sW[D * NHEADS + h], acc[h]);
    }
    #pragma unroll
    for (int h = 0; h < NHEADS; h++)
        g_costE[((size_t)b * NHEADS + h) * WIDTH + w] = expf(acc[h]);
}

// ============================================================
// Kernel 2: denominator conv -> reciprocal
// ============================================================
__global__ void __launch_bounds__(256) denom_kernel(const float* __restrict__ rpe) {
    __shared__ float s[256 + 32];
    __shared__ float rks[KSZ];
    int h = blockIdx.y;
    int b = blockIdx.z;
    int w0 = blockIdx.x * 256;
    int tid = threadIdx.x;
    if (tid < KSZ) rks[tid] = expf(rpe[h * KSZ + tid]);
    const float* crow = g_costE + ((size_t)b * NHEADS + h) * WIDTH;
    #pragma unroll
    for (int i = tid; i < 256 + 32; i += 256) {
        int g = w0 - PADW + i;
        s[i] = (g >= 0 && g < WIDTH) ? crow[g] : 0.f;
    }
    __syncthreads();
    float rkr[KSZ];
    #pragma unroll
    for (int k = 0; k < KSZ; k++) rkr[k] = rks[k];
    float sc = 0.f;
    #pragma unroll
    for (int k = 0; k < KSZ; k++) sc = fmaf(s[tid + k], rkr[k], sc);
    g_rinv[((size_t)b * NHEADS + h) * WIDTH + w0 + tid] = 1.0f / sc;
}

// ============================================================
// Kernel 3: 31-tap conv on vc * rinv
// ============================================================
#define CTILE 1024
__global__ void __launch_bounds__(256) conv_kernel(const float* __restrict__ rpe) {
    __shared__ __align__(16) float s[CTILE + 36];
    __shared__ float rks[KSZ];
    int c = blockIdx.y;
    int h = c >> 5;
    int b = blockIdx.z;
    int w0 = blockIdx.x * CTILE;
    int tid = threadIdx.x;
    if (tid < KSZ) rks[tid] = expf(rpe[h * KSZ + tid]);

    const float* vrow = g_vc + ((size_t)b * HIDCH + c) * WIDTH;
    #pragma unroll
    for (int i = tid; i < CTILE + 36; i += 256) {
        int g = w0 - PADW + i;
        s[i] = (g >= 0 && g < WIDTH) ? __ldg(vrow + g) : 0.f;
    }
    __syncthreads();

    float rkr[KSZ];
    #pragma unroll
    for (int k = 0; k < KSZ; k++) rkr[k] = rks[k];

    const int t4 = tid * 4;
    float a0 = 0.f, a1 = 0.f, a2 = 0.f, a3 = 0.f;
    #pragma unroll
    for (int u = 0; u < 9; u++) {
        float4 v4 = *(const float4*)&s[t4 + u * 4];
        float vv[4] = {v4.x, v4.y, v4.z, v4.w};
        #pragma unroll
        for (int e = 0; e < 4; e++) {
            const int m = u * 4 + e;
            if (m >= 0 && m < KSZ)         a0 = fmaf(vv[e], rkr[m],     a0);
            if (m - 1 >= 0 && m - 1 < KSZ) a1 = fmaf(vv[e], rkr[m - 1], a1);
            if (m - 2 >= 0 && m - 2 < KSZ) a2 = fmaf(vv[e], rkr[m - 2], a2);
            if (m - 3 >= 0 && m - 3 < KSZ) a3 = fmaf(vv[e], rkr[m - 3], a3);
        }
    }
    const float* rinv = g_rinv + ((size_t)b * NHEADS + h) * WIDTH + w0 + t4;
    float4 ri = *(const float4*)rinv;
    float4 o;
    o.x = a0 * ri.x;
    o.y = a1 * ri.y;
    o.z = a2 * ri.z;
    o.w = a3 * ri.w;
    *(float4*)&g_r[((size_t)b * HIDCH + c) * WIDTH + w0 + t4] = o;
}

// ============================================================
// HMMA bf16x3 GEMM:  C[c][w] = sum_k W[c][k] * X[k][w]
//   M = c (128/block), N = w (128/block), K chunks of 32.
//   A = W tile [c][k] row-major (ldmatrix.x4)
//   B = X tile [k][w] natural  (ldmatrix.x2.trans => col-major frags)
//   D += Ahi*Bhi + Ahi*Blo + Alo*Bhi   (fp32 accum)
//   8 warps: warp_m = wid>>2 (64 c), warp_n = wid&3 (32 w).
// ============================================================
#define SA_STRIDE 80     // bytes per A row (32 bf16 = 64B data + 16 pad)
#define SB_STRIDE 272    // bytes per B k-row (128 bf16 = 256B data + 16 pad)
#define OFF_AHI 0
#define OFF_ALO 10240    // 128*80
#define OFF_BHI 20480
#define OFF_BLO 29184    // +32*272
#define STG_SZ  37888
#define SM_STG  1024
#define SM_TOT_MMA (SM_STG + 2 * STG_SZ)   // 76800

template <int MODE>
__global__ void __launch_bounds__(256, 1)
gemm_mma(const float* __restrict__ Wt,
         const float* __restrict__ Xg,
         const float* __restrict__ bias,
         float* __restrict__ Out) {
    extern __shared__ __align__(16) char smem[];
    const uint32_t sbu = smem_to_u32(smem);
    float* sbias = (float*)smem;                      // 128 floats at offset 0

    const int tid  = threadIdx.x;
    const int wid  = tid >> 5;
    const int lane = tid & 31;
    const int warp_m = wid >> 2;       // 0..1  (c)
    const int warp_n = wid & 3;        // 0..3  (w)
    const int bn = blockIdx.x * 128;   // w base
    const int cm = blockIdx.y * 128;   // c base
    const int b  = blockIdx.z;

    const float* Xb = (MODE == 0) ? (Xg + (size_t)b * CINCH * WIDTH)
                                  : (g_r + (size_t)b * HIDCH * WIDTH);

    if (tid < 128) sbias[tid] = bias[cm + tid];

    // accumulators: d[mi][ni][4]
    float d[4][4][4];
    #pragma unroll
    for (int mi = 0; mi < 4; mi++)
        #pragma unroll
        for (int ni = 0; ni < 4; ni++)
            #pragma unroll
            for (int e = 0; e < 4; e++) d[mi][ni][e] = 0.f;

    // prefetch regs
    float4 pa[4], pb[4];
    {
        #pragma unroll
        for (int j = 0; j < 4; j++) {
            int u = tid + j * 256;
            int r = u >> 3, f4 = u & 7;
            pa[j] = *(const float4*)(Wt + (size_t)(cm + r) * CINCH + 0 + f4 * 4);
            int k = u >> 5, wq = u & 31;
            pb[j] = *(const float4*)(Xb + (size_t)(0 + k) * WIDTH + bn + wq * 4);
        }
    }

    for (int i = 0; i < 8; i++) {
        if (i) __syncthreads();
        char* stg = smem + SM_STG + (i & 1) * STG_SZ;
        // ---- convert + store chunk i ----
        #pragma unroll
        for (int j = 0; j < 4; j++) {
            int u = tid + j * 256;
            {   // A
                int r = u >> 3, f4 = u & 7;
                float v[4] = {pa[j].x, pa[j].y, pa[j].z, pa[j].w};
                uint16_t h[4], l[4];
                #pragma unroll
                for (int e = 0; e < 4; e++) split_bf16(v[e], h[e], l[e]);
                uint2 hp, lp;
                hp.x = (uint32_t)h[0] | ((uint32_t)h[1] << 16);
                hp.y = (uint32_t)h[2] | ((uint32_t)h[3] << 16);
                lp.x = (uint32_t)l[0] | ((uint32_t)l[1] << 16);
                lp.y = (uint32_t)l[2] | ((uint32_t)l[3] << 16);
                *(uint2*)(stg + OFF_AHI + r * SA_STRIDE + f4 * 8) = hp;
                *(uint2*)(stg + OFF_ALO + r * SA_STRIDE + f4 * 8) = lp;
            }
            {   // B
                int k = u >> 5, wq = u & 31;
                float v[4] = {pb[j].x, pb[j].y, pb[j].z, pb[j].w};
                uint16_t h[4], l[4];
                #pragma unroll
                for (int e = 0; e < 4; e++) split_bf16(v[e], h[e], l[e]);
                uint2 hp, lp;
                hp.x = (uint32_t)h[0] | ((uint32_t)h[1] << 16);
                hp.y = (uint32_t)h[2] | ((uint32_t)h[3] << 16);
                lp.x = (uint32_t)l[0] | ((uint32_t)l[1] << 16);
                lp.y = (uint32_t)l[2] | ((uint32_t)l[3] << 16);
                *(uint2*)(stg + OFF_BHI + k * SB_STRIDE + wq * 8) = hp;
                *(uint2*)(stg + OFF_BLO + k * SB_STRIDE + wq * 8) = lp;
            }
        }
        __syncthreads();
        // ---- prefetch chunk i+1 ----
        if (i < 7) {
            int k0 = (i + 1) * 32;
            #pragma unroll
            for (int j = 0; j < 4; j++) {
                int u = tid + j * 256;
                int r = u >> 3, f4 = u & 7;
                pa[j] = *(const float4*)(Wt + (size_t)(cm + r) * CINCH + k0 + f4 * 4);
                int k = u >> 5, wq = u & 31;
                pb[j] = *(const float4*)(Xb + (size_t)(k0 + k) * WIDTH + bn + wq * 4);
            }
        }
        // ---- compute on chunk i ----
        const uint32_t stgb = sbu + SM_STG + (i & 1) * STG_SZ;
        #pragma unroll
        for (int ks = 0; ks < 2; ks++) {
            uint32_t ah[4][4], al[4][4];
            #pragma unroll
            for (int mi = 0; mi < 4; mi++) {
                uint32_t addr = stgb + OFF_AHI
                    + (uint32_t)(warp_m * 64 + mi * 16 + (lane & 15)) * SA_STRIDE
                    + ks * 32 + (lane >> 4) * 16;
                ldsm_x4(ah[mi], addr);
                ldsm_x4(al[mi], addr + (OFF_ALO - OFF_AHI));
            }
            uint32_t bh[4][2], bl[4][2];
            #pragma unroll
            for (int ni = 0; ni < 4; ni++) {
                uint32_t addr = stgb + OFF_BHI
                    + (uint32_t)(ks * 16 + (lane & 15)) * SB_STRIDE
                    + (warp_n * 32 + ni * 8) * 2;
                ldsm_x2t(bh[ni], addr);
                ldsm_x2t(bl[ni], addr + (OFF_BLO - OFF_BHI));
            }
            #pragma unroll
            for (int mi = 0; mi < 4; mi++)
                #pragma unroll
                for (int ni = 0; ni < 4; ni++)
                    mma_bf16(d[mi][ni], ah[mi], bh[ni]);
            #pragma unroll
            for (int mi = 0; mi < 4; mi++)
                #pragma unroll
                for (int ni = 0; ni < 4; ni++)
                    mma_bf16(d[mi][ni], ah[mi], bl[ni]);
            #pragma unroll
            for (int mi = 0; mi < 4; mi++)
                #pragma unroll
                for (int ni = 0; ni < 4; ni++)
                    mma_bf16(d[mi][ni], al[mi], bh[ni]);
        }
    }

    // ---- epilogue ----
    #pragma unroll
    for (int mi = 0; mi < 4; mi++) {
        int cl0 = warp_m * 64 + mi * 16 + (lane >> 2);   // local c, row 0
        int c0 = cm + cl0;
        int h = c0 >> 5;
        float bv0 = sbias[cl0];
        float bv1 = sbias[cl0 + 8];
        #pragma unroll
        for (int ni = 0; ni < 4; ni++) {
            int w0 = bn + warp_n * 32 + ni * 8 + (lane & 3) * 2;
            float2 o0, o1;
            if (MODE == 0) {
                float2 ce = *(const float2*)&g_costE[((size_t)b * NHEADS + h) * WIDTH + w0];
                o0.x = ce.x * (d[mi][ni][0] + bv0);
                o0.y = ce.y * (d[mi][ni][1] + bv0);
                o1.x = ce.x * (d[mi][ni][2] + bv1);
                o1.y = ce.y * (d[mi][ni][3] + bv1);
                *(float2*)&g_vc[((size_t)b * HIDCH + c0) * WIDTH + w0]     = o0;
                *(float2*)&g_vc[((size_t)b * HIDCH + c0 + 8) * WIDTH + w0] = o1;
            } else {
                o0.x = d[mi][ni][0] + bv0;
                o0.y = d[mi][ni][1] + bv0;
                o1.x = d[mi][ni][2] + bv1;
                o1.y = d[mi][ni][3] + bv1;
                *(float2*)&Out[((size_t)b * HIDCH + c0) * WIDTH + w0]     = o0;
                *(float2*)&Out[((size_t)b * HIDCH + c0 + 8) * WIDTH + w0] = o1;
            }
        }
    }
}

// ============================================================
extern "C" void kernel_launch(void* const* d_in, const int* in_sizes, int n_in,
                              void* d_out, int out_size) {
    const float* x     = (const float*)d_in[0];
    const float* query = (const float*)d_in[1];
    const float* Wk    = (const float*)d_in[2];
    const float* Wkb   = (const float*)d_in[3];
    const float* rpe   = (const float*)d_in[4];
    const float* Wv    = (const float*)d_in[5];
    const float* bv    = (const float*)d_in[6];
    const float* Wo    = (const float*)d_in[7];
    const float* bo    = (const float*)d_in[8];
    float* out = (float*)d_out;

    cudaFuncSetAttribute(gemm_mma<0>, cudaFuncAttributeMaxDynamicSharedMemorySize, SM_TOT_MMA);
    cudaFuncSetAttribute(gemm_mma<1>, cudaFuncAttributeMaxDynamicSharedMemorySize, SM_TOT_MMA);

    precompute_kernel<<<1, 256>>>(query, Wk, Wkb);
    cost_kernel<<<dim3(WIDTH / 256, BATCH), 256>>>(x);
    denom_kernel<<<dim3(WIDTH / 256, NHEADS, BATCH), 256>>>(rpe);
    gemm_mma<0><<<dim3(WIDTH / 128, HIDCH / 128, BATCH), 256, SM_TOT_MMA>>>(Wv, x, bv, nullptr);
    conv_kernel<<<dim3(WIDTH / CTILE, HIDCH, BATCH), 256>>>(rpe);
    gemm_mma<1><<<dim3(WIDTH / 128, HIDCH / 128, BATCH), 256, SM_TOT_MMA>>>(Wo, nullptr, bo, out);
}

// round 8
// speedup vs baseline: 1.8104x; 1.1160x over previous
#include <cuda_runtime.h>
#include <cuda_bf16.h>
#include <cstdint>
#include <math.h>

#define BATCH  8
#define CINCH  256
#define HIDCH  256
#define NHEADS 8
#define HDIM   32
#define KSZ    31
#define PADW   15
#define WIDTH  16384

// ---- scratch (device globals; no allocation allowed) ----
__device__ float g_qWk[CINCH * NHEADS];
__device__ float g_qb[NHEADS];
__device__ float g_costE[BATCH * NHEADS * WIDTH];                 // 4 MB
__device__ float g_rinv [BATCH * NHEADS * WIDTH];                 // 4 MB
__device__ float g_vc[(size_t)BATCH * HIDCH * WIDTH];             // 128 MB
__device__ __nv_bfloat16 g_xhi[(size_t)BATCH * CINCH * WIDTH];    // 64 MB
__device__ __nv_bfloat16 g_xlo[(size_t)BATCH * CINCH * WIDTH];    // 64 MB
__device__ __nv_bfloat16 g_rhi[(size_t)BATCH * HIDCH * WIDTH];    // 64 MB
__device__ __nv_bfloat16 g_rlo[(size_t)BATCH * HIDCH * WIDTH];    // 64 MB
__device__ __nv_bfloat16 g_wvhi[HIDCH * CINCH];
__device__ __nv_bfloat16 g_wvlo[HIDCH * CINCH];
__device__ __nv_bfloat16 g_wohi[HIDCH * HIDCH];
__device__ __nv_bfloat16 g_wolo[HIDCH * HIDCH];

// ============================================================
// helpers
// ============================================================
__device__ __forceinline__ uint32_t smem_to_u32(const void* p) {
    uint32_t a;
    asm("{ .reg .u64 t; cvta.to.shared.u64 t, %1; cvt.u32.u64 %0, t; }" : "=r"(a) : "l"(p));
    return a;
}
__device__ __forceinline__ void ldsm_x4(uint32_t* r, uint32_t addr) {
    asm volatile("ldmatrix.sync.aligned.m8n8.x4.shared.b16 {%0,%1,%2,%3}, [%4];"
                 : "=r"(r[0]), "=r"(r[1]), "=r"(r[2]), "=r"(r[3]) : "r"(addr));
}
__device__ __forceinline__ void ldsm_x2t(uint32_t* r, uint32_t addr) {
    asm volatile("ldmatrix.sync.aligned.m8n8.x2.trans.shared.b16 {%0,%1}, [%2];"
                 : "=r"(r[0]), "=r"(r[1]) : "r"(addr));
}
__device__ __forceinline__ void mma_bf16(float* d, const uint32_t* a, const uint32_t* b) {
    asm volatile("mma.sync.aligned.m16n8k16.row.col.f32.bf16.bf16.f32 "
                 "{%0,%1,%2,%3}, {%4,%5,%6,%7}, {%8,%9}, {%0,%1,%2,%3};"
                 : "+f"(d[0]), "+f"(d[1]), "+f"(d[2]), "+f"(d[3])
                 : "r"(a[0]), "r"(a[1]), "r"(a[2]), "r"(a[3]),
                   "r"(b[0]), "r"(b[1]));
}
__device__ __forceinline__ void split_bf16(float v, __nv_bfloat16& hi, __nv_bfloat16& lo) {
    hi = __float2bfloat16_rn(v);
    lo = __float2bfloat16_rn(v - __bfloat162float(hi));
}
__device__ __forceinline__ void cp_async16(uint32_t dst, const void* src) {
    asm volatile("cp.async.cg.shared.global [%0], [%1], 16;" :: "r"(dst), "l"(src));
}
#define CP_COMMIT() asm volatile("cp.async.commit_group;" ::: "memory")
#define CP_WAIT(n)  asm volatile("cp.async.wait_group %0;" :: "n"(n) : "memory")

// ============================================================
// Kernel 0: precompute qWk[D][h], qb[h]
// ============================================================
__global__ void precompute_kernel(const float* __restrict__ query,
                                  const float* __restrict__ Wk,
                                  const float* __restrict__ Wkb) {
    __shared__ float sq[CINCH];
    __shared__ float qn[CINCH];
    __shared__ float nrm[NHEADS];
    int tid = threadIdx.x;
    float qv = query[tid];
    sq[tid] = qv * qv;
    __syncthreads();
    if (tid < NHEADS) {
        float s = 0.f;
        #pragma unroll
        for (int d = 0; d < HDIM; d++) s += sq[tid * HDIM + d];
        nrm[tid] = sqrtf(s) + 1e-6f;
    }
    __syncthreads();
    qn[tid] = qv / nrm[tid / HDIM] * 0.17677669529663687f;
    __syncthreads();
    int D = tid;
    #pragma unroll
    for (int h = 0; h < NHEADS; h++) {
        float s = 0.f;
        const float* wrow = Wk + D * HIDCH + h * HDIM;
        #pragma unroll
        for (int d = 0; d < HDIM; d++) s += qn[h * HDIM + d] * wrow[d];
        g_qWk[D * NHEADS + h] = s;
    }
    if (tid < NHEADS) {
        float s = 0.f;
        #pragma unroll
        for (int d = 0; d < HDIM; d++) s += Wkb[tid * HDIM + d] * qn[tid * HDIM + d];
        g_qb[tid] = s;
    }
}

// ============================================================
// Weight split: W[65536] fp32 -> hi/lo bf16 planes
// ============================================================
__global__ void wsplit_kernel(const float* __restrict__ W,
                              __nv_bfloat16* __restrict__ hi,
                              __nv_bfloat16* __restrict__ lo) {
    int base = (blockIdx.x * 256 + threadIdx.x) * 8;
    float4 v0 = *(const float4*)(W + base);
    float4 v1 = *(const float4*)(W + base + 4);
    float v[8] = {v0.x, v0.y, v0.z, v0.w, v1.x, v1.y, v1.z, v1.w};
    __nv_bfloat16 h[8], l[8];
    #pragma unroll
    for (int e = 0; e < 8; e++) split_bf16(v[e], h[e], l[e]);
    *(uint4*)(hi + base) = *(uint4*)h;
    *(uint4*)(lo + base) = *(uint4*)l;
}

// ============================================================
// X split: x fp32 -> g_xhi / g_xlo
// ============================================================
__global__ void __launch_bounds__(256) xsplit_kernel(const float* __restrict__ x) {
    size_t base = ((size_t)blockIdx.x * 256 + threadIdx.x) * 8;
    float4 v0 = *(const float4*)(x + base);
    float4 v1 = *(const float4*)(x + base + 4);
    float v[8] = {v0.x, v0.y, v0.z, v0.w, v1.x, v1.y, v1.z, v1.w};
    __nv_bfloat16 h[8], l[8];
    #pragma unroll
    for (int e = 0; e < 8; e++) split_bf16(v[e], h[e], l[e]);
    *(uint4*)(g_xhi + base) = *(uint4*)h;
    *(uint4*)(g_xlo + base) = *(uint4*)l;
}

// ============================================================
// Kernel 1: cost_exp[b][h][w]
// ============================================================
__global__ void __launch_bounds__(256) cost_kernel(const float* __restrict__ x) {
    __shared__ float sW[CINCH * NHEADS];
    __shared__ float sb[NHEADS];
    int tid = threadIdx.x;
    for (int i = tid; i < CINCH * NHEADS; i += 256) sW[i] = g_qWk[i];
    if (tid < NHEADS) sb[tid] = g_qb[tid];
    __syncthreads();

    int b = blockIdx.y;
    int w = blockIdx.x * 256 + tid;
    const float* xb = x + (size_t)b * CINCH * WIDTH + w;

    float acc[NHEADS];
    #pragma unroll
    for (int h = 0; h < NHEADS; h++) acc[h] = sb[h];

    for (int D = 0; D < CINCH; D++) {
        float v = __ldg(xb + (size_t)D * WIDTH);
        #pragma unroll
        for (int h = 0; h < NHEADS; h++) acc[h] = fmaf(v, sW[D * NHEADS + h], acc[h]);
    }
    #pragma unroll
    for (int h = 0; h < NHEADS; h++)
        g_costE[((size_t)b * NHEADS + h) * WIDTH + w] = expf(acc[h]);
}

// ============================================================
// Kernel 2: denominator conv -> reciprocal
// ============================================================
__global__ void __launch_bounds__(256) denom_kernel(const float* __restrict__ rpe) {
    __shared__ float s[256 + 32];
    __shared__ float rks[KSZ];
    int h = blockIdx.y;
    int b = blockIdx.z;
    int w0 = blockIdx.x * 256;
    int tid = threadIdx.x;
    if (tid < KSZ) rks[tid] = expf(rpe[h * KSZ + tid]);
    const float* crow = g_costE + ((size_t)b * NHEADS + h) * WIDTH;
    #pragma unroll
    for (int i = tid; i < 256 + 32; i += 256) {
        int g = w0 - PADW + i;
        s[i] = (g >= 0 && g < WIDTH) ? crow[g] : 0.f;
    }
    __syncthreads();
    float rkr[KSZ];
    #pragma unroll
    for (int k = 0; k < KSZ; k++) rkr[k] = rks[k];
    float sc = 0.f;
    #pragma unroll
    for (int k = 0; k < KSZ; k++) sc = fmaf(s[tid + k], rkr[k], sc);
    g_rinv[((size_t)b * NHEADS + h) * WIDTH + w0 + tid] = 1.0f / sc;
}

// ============================================================
// Kernel 3: 31-tap conv on vc * rinv -> bf16 hi/lo planes
// ============================================================
#define CTILE 1024
__global__ void __launch_bounds__(256) conv_kernel(const float* __restrict__ rpe) {
    __shared__ __align__(16) float s[CTILE + 36];
    __shared__ float rks[KSZ];
    int c = blockIdx.y;
    int h = c >> 5;
    int b = blockIdx.z;
    int w0 = blockIdx.x * CTILE;
    int tid = threadIdx.x;
    if (tid < KSZ) rks[tid] = expf(rpe[h * KSZ + tid]);

    const float* vrow = g_vc + ((size_t)b * HIDCH + c) * WIDTH;
    #pragma unroll
    for (int i = tid; i < CTILE + 36; i += 256) {
        int g = w0 - PADW + i;
        s[i] = (g >= 0 && g < WIDTH) ? __ldg(vrow + g) : 0.f;
    }
    __syncthreads();

    float rkr[KSZ];
    #pragma unroll
    for (int k = 0; k < KSZ; k++) rkr[k] = rks[k];

    const int t4 = tid * 4;
    float a0 = 0.f, a1 = 0.f, a2 = 0.f, a3 = 0.f;
    #pragma unroll
    for (int u = 0; u < 9; u++) {
        float4 v4 = *(const float4*)&s[t4 + u * 4];
        float vv[4] = {v4.x, v4.y, v4.z, v4.w};
        #pragma unroll
        for (int e = 0; e < 4; e++) {
            const int m = u * 4 + e;
            if (m >= 0 && m < KSZ)         a0 = fmaf(vv[e], rkr[m],     a0);
            if (m - 1 >= 0 && m - 1 < KSZ) a1 = fmaf(vv[e], rkr[m - 1], a1);
            if (m - 2 >= 0 && m - 2 < KSZ) a2 = fmaf(vv[e], rkr[m - 2], a2);
            if (m - 3 >= 0 && m - 3 < KSZ) a3 = fmaf(vv[e], rkr[m - 3], a3);
        }
    }
    const float* rinv = g_rinv + ((size_t)b * NHEADS + h) * WIDTH + w0 + t4;
    float4 ri = *(const float4*)rinv;
    float o[4];
    o[0] = a0 * ri.x;
    o[1] = a1 * ri.y;
    o[2] = a2 * ri.z;
    o[3] = a3 * ri.w;
    __nv_bfloat16 hh[4], ll[4];
    #pragma unroll
    for (int e = 0; e < 4; e++) split_bf16(o[e], hh[e], ll[e]);
    size_t obase = ((size_t)b * HIDCH + c) * WIDTH + w0 + t4;
    *(uint2*)(g_rhi + obase) = *(uint2*)hh;
    *(uint2*)(g_rlo + obase) = *(uint2*)ll;
}

// ============================================================
// HMMA bf16x3 GEMM (cp.async pipelined, pre-split operands)
//   C[c][w] = sum_k W[c][k] * X[k][w]
//   A = W hi/lo [c][k] (ldmatrix.x4), B = X hi/lo [k][w] (ldmatrix.x2.trans)
//   D += Ahi*Bhi + Alo*Bhi + Ahi*Blo
// ============================================================
#define SA_STRIDE 80     // bytes per A row (32 bf16 + 16B pad)
#define SB_STRIDE 272    // bytes per B k-row (128 bf16 + 16B pad)
#define OFF_AHI 0
#define OFF_ALO 10240
#define OFF_BHI 20480
#define OFF_BLO 29184
#define STG_SZ  37888
#define SM_STG  1024
#define SM_TOT_MMA (SM_STG + 2 * STG_SZ)   // 76800

template <int MODE>
__global__ void __launch_bounds__(256, 2)
gemm_mma(const float* __restrict__ bias, float* __restrict__ Out) {
    extern __shared__ __align__(16) char smem[];
    const uint32_t sbu = smem_to_u32(smem);
    float* sbias = (float*)smem;

    const int tid  = threadIdx.x;
    const int wid  = tid >> 5;
    const int lane = tid & 31;
    const int warp_m = wid >> 2;
    const int warp_n = wid & 3;
    const int bn = blockIdx.x * 128;   // w base
    const int cm = blockIdx.y * 128;   // c base
    const int b  = blockIdx.z;

    const __nv_bfloat16* Whi = (MODE == 0) ? g_wvhi : g_wohi;
    const __nv_bfloat16* Wlo = (MODE == 0) ? g_wvlo : g_wolo;
    const __nv_bfloat16* Xhi = ((MODE == 0) ? g_xhi : g_rhi) + (size_t)b * CINCH * WIDTH;
    const __nv_bfloat16* Xlo = ((MODE == 0) ? g_xlo : g_rlo) + (size_t)b * CINCH * WIDTH;

    if (tid < 128) sbias[tid] = bias[cm + tid];

    const int av0 = tid * 2;
    auto issue = [&](int chunk, int slot) {
        const uint32_t stgu = sbu + SM_STG + slot * STG_SZ;
        const int k0 = chunk * 32;
        #pragma unroll
        for (int j = 0; j < 2; j++) {
            int v = av0 + j;
            int r = v >> 2, c4 = v & 3;
            const __nv_bfloat16* sh = Whi + (size_t)(cm + r) * CINCH + k0 + c4 * 8;
            const __nv_bfloat16* sl = Wlo + (size_t)(cm + r) * CINCH + k0 + c4 * 8;
            cp_async16(stgu + OFF_AHI + r * SA_STRIDE + c4 * 16, sh);
            cp_async16(stgu + OFF_ALO + r * SA_STRIDE + c4 * 16, sl);
        }
        #pragma unroll
        for (int j = 0; j < 2; j++) {
            int v = av0 + j;
            int r = v >> 4, c = v & 15;
            const __nv_bfloat16* sh = Xhi + (size_t)(k0 + r) * WIDTH + bn + c * 8;
            const __nv_bfloat16* sl = Xlo + (size_t)(k0 + r) * WIDTH + bn + c * 8;
            cp_async16(stgu + OFF_BHI + r * SB_STRIDE + c * 16, sh);
            cp_async16(stgu + OFF_BLO + r * SB_STRIDE + c * 16, sl);
        }
        CP_COMMIT();
    };

    float d[4][4][4];
    #pragma unroll
    for (int mi = 0; mi < 4; mi++)
        #pragma unroll
        for (int ni = 0; ni < 4; ni++)
            #pragma unroll
            for (int e = 0; e < 4; e++) d[mi][ni][e] = 0.f;

    issue(0, 0);

    for (int i = 0; i < 8; i++) {
        if (i < 7) issue(i + 1, (i + 1) & 1);
        if (i < 7) { CP_WAIT(1); } else { CP_WAIT(0); }
        __syncthreads();

        const uint32_t stgb = sbu + SM_STG + (i & 1) * STG_SZ;
        #pragma unroll
        for (int ks = 0; ks < 2; ks++) {
            uint32_t ah[4][4], al[4][4];
            #pragma unroll
            for (int mi = 0; mi < 4; mi++) {
                uint32_t addr = stgb + OFF_AHI
                    + (uint32_t)(warp_m * 64 + mi * 16 + (lane & 15)) * SA_STRIDE
                    + ks * 32 + (lane >> 4) * 16;
                ldsm_x4(ah[mi], addr);
                ldsm_x4(al[mi], addr + (OFF_ALO - OFF_AHI));
            }
            #pragma unroll
            for (int ni = 0; ni < 4; ni++) {
                uint32_t addr = stgb + OFF_BHI
                    + (uint32_t)(ks * 16 + (lane & 15)) * SB_STRIDE
                    + (warp_n * 32 + ni * 8) * 2;
                uint32_t bh[2], bl[2];
                ldsm_x2t(bh, addr);
                ldsm_x2t(bl, addr + (OFF_BLO - OFF_BHI));
                #pragma unroll
                for (int mi = 0; mi < 4; mi++) mma_bf16(d[mi][ni], ah[mi], bh);
                #pragma unroll
                for (int mi = 0; mi < 4; mi++) mma_bf16(d[mi][ni], al[mi], bh);
                #pragma unroll
                for (int mi = 0; mi < 4; mi++) mma_bf16(d[mi][ni], ah[mi], bl);
            }
        }
        __syncthreads();
    }

    // ---- epilogue ----
    #pragma unroll
    for (int mi = 0; mi < 4; mi++) {
        int cl0 = warp_m * 64 + mi * 16 + (lane >> 2);
        int c0 = cm + cl0;
        int h = c0 >> 5;
        float bv0 = sbias[cl0];
        float bv1 = sbias[cl0 + 8];
        #pragma unroll
        for (int ni = 0; ni < 4; ni++) {
            int w0 = bn + warp_n * 32 + ni * 8 + (lane & 3) * 2;
            float2 o0, o1;
            if (MODE == 0) {
                float2 ce = *(const float2*)&g_costE[((size_t)b * NHEADS + h) * WIDTH + w0];
                o0.x = ce.x * (d[mi][ni][0] + bv0);
                o0.y = ce.y * (d[mi][ni][1] + bv0);
                o1.x = ce.x * (d[mi][ni][2] + bv1);
                o1.y = ce.y * (d[mi][ni][3] + bv1);
                *(float2*)&g_vc[((size_t)b * HIDCH + c0) * WIDTH + w0]     = o0;
                *(float2*)&g_vc[((size_t)b * HIDCH + c0 + 8) * WIDTH + w0] = o1;
            } else {
                o0.x = d[mi][ni][0] + bv0;
                o0.y = d[mi][ni][1] + bv0;
                o1.x = d[mi][ni][2] + bv1;
                o1.y = d[mi][ni][3] + bv1;
                *(float2*)&Out[((size_t)b * HIDCH + c0) * WIDTH + w0]     = o0;
                *(float2*)&Out[((size_t)b * HIDCH + c0 + 8) * WIDTH + w0] = o1;
            }
        }
    }
}

// ============================================================
extern "C" void kernel_launch(void* const* d_in, const int* in_sizes, int n_in,
                              void* d_out, int out_size) {
    const float* x     = (const float*)d_in[0];
    const float* query = (const float*)d_in[1];
    const float* Wk    = (const float*)d_in[2];
    const float* Wkb   = (const float*)d_in[3];
    const float* rpe   = (const float*)d_in[4];
    const float* Wv    = (const float*)d_in[5];
    const float* bv    = (const float*)d_in[6];
    const float* Wo    = (const float*)d_in[7];
    const float* bo    = (const float*)d_in[8];
    float* out = (float*)d_out;

    cudaFuncSetAttribute(gemm_mma<0>, cudaFuncAttributeMaxDynamicSharedMemorySize, SM_TOT_MMA);
    cudaFuncSetAttribute(gemm_mma<1>, cudaFuncAttributeMaxDynamicSharedMemorySize, SM_TOT_MMA);

    precompute_kernel<<<1, 256>>>(query, Wk, Wkb);
    {
        __nv_bfloat16 *dvh, *dvl, *doh, *dol;
        cudaGetSymbolAddress((void**)&dvh, g_wvhi);
        cudaGetSymbolAddress((void**)&dvl, g_wvlo);
        cudaGetSymbolAddress((void**)&doh, g_wohi);
        cudaGetSymbolAddress((void**)&dol, g_wolo);
        wsplit_kernel<<<32, 256>>>(Wv, dvh, dvl);
        wsplit_kernel<<<32, 256>>>(Wo, doh, dol);
    }
    xsplit_kernel<<<(BATCH * CINCH * WIDTH) / (256 * 8), 256>>>(x);
    cost_kernel<<<dim3(WIDTH / 256, BATCH), 256>>>(x);
    denom_kernel<<<dim3(WIDTH / 256, NHEADS, BATCH), 256>>>(rpe);
    gemm_mma<0><<<dim3(WIDTH / 128, HIDCH / 128, BATCH), 256, SM_TOT_MMA>>>(bv, nullptr);
    conv_kernel<<<dim3(WIDTH / CTILE, HIDCH, BATCH), 256>>>(rpe);
    gemm_mma<1><<<dim3(WIDTH / 128, HIDCH / 128, BATCH), 256, SM_TOT_MMA>>>(bo, out);
}

// round 9
// speedup vs baseline: 2.2721x; 1.2550x over previous
#include <cuda_runtime.h>
#include <cuda_fp16.h>
#include <cstdint>
#include <math.h>

#define BATCH  8
#define CINCH  256
#define HIDCH  256
#define NHEADS 8
#define HDIM   32
#define KSZ    31
#define PADW   15
#define WIDTH  16384

// ---- scratch (device globals; no allocation allowed) ----
__device__ float g_qWk[CINCH * NHEADS];
__device__ float g_qb[NHEADS];
__device__ float g_costE[BATCH * NHEADS * WIDTH];                 // 4 MB
__device__ float g_rinv [BATCH * NHEADS * WIDTH];                 // 4 MB
__device__ float g_vc[(size_t)BATCH * HIDCH * WIDTH];             // 128 MB
__device__ __half g_xh[(size_t)BATCH * CINCH * WIDTH];            // 64 MB
__device__ __half g_rh[(size_t)BATCH * HIDCH * WIDTH];            // 64 MB
__device__ __half g_wvhi[HIDCH * CINCH];
__device__ __half g_wvlo[HIDCH * CINCH];
__device__ __half g_wohi[HIDCH * HIDCH];
__device__ __half g_wolo[HIDCH * HIDCH];

// ============================================================
// helpers
// ============================================================
__device__ __forceinline__ uint32_t smem_to_u32(const void* p) {
    uint32_t a;
    asm("{ .reg .u64 t; cvta.to.shared.u64 t, %1; cvt.u32.u64 %0, t; }" : "=r"(a) : "l"(p));
    return a;
}
__device__ __forceinline__ void ldsm_x4(uint32_t* r, uint32_t addr) {
    asm volatile("ldmatrix.sync.aligned.m8n8.x4.shared.b16 {%0,%1,%2,%3}, [%4];"
                 : "=r"(r[0]), "=r"(r[1]), "=r"(r[2]), "=r"(r[3]) : "r"(addr));
}
__device__ __forceinline__ void ldsm_x2t(uint32_t* r, uint32_t addr) {
    asm volatile("ldmatrix.sync.aligned.m8n8.x2.trans.shared.b16 {%0,%1}, [%2];"
                 : "=r"(r[0]), "=r"(r[1]) : "r"(addr));
}
__device__ __forceinline__ void mma_f16(float* d, const uint32_t* a, const uint32_t* b) {
    asm volatile("mma.sync.aligned.m16n8k16.row.col.f32.f16.f16.f32 "
                 "{%0,%1,%2,%3}, {%4,%5,%6,%7}, {%8,%9}, {%0,%1,%2,%3};"
                 : "+f"(d[0]), "+f"(d[1]), "+f"(d[2]), "+f"(d[3])
                 : "r"(a[0]), "r"(a[1]), "r"(a[2]), "r"(a[3]),
                   "r"(b[0]), "r"(b[1]));
}
__device__ __forceinline__ void split_f16(float v, __half& hi, __half& lo) {
    hi = __float2half_rn(v);
    lo = __float2half_rn(v - __half2float(hi));
}
__device__ __forceinline__ void cp_async16(uint32_t dst, const void* src) {
    asm volatile("cp.async.cg.shared.global [%0], [%1], 16;" :: "r"(dst), "l"(src));
}
#define CP_COMMIT() asm volatile("cp.async.commit_group;" ::: "memory")
#define CP_WAIT(n)  asm volatile("cp.async.wait_group %0;" :: "n"(n) : "memory")

// ============================================================
// Kernel 0: precompute qWk[D][h], qb[h]
// ============================================================
__global__ void precompute_kernel(const float* __restrict__ query,
                                  const float* __restrict__ Wk,
                                  const float* __restrict__ Wkb) {
    __shared__ float sq[CINCH];
    __shared__ float qn[CINCH];
    __shared__ float nrm[NHEADS];
    int tid = threadIdx.x;
    float qv = query[tid];
    sq[tid] = qv * qv;
    __syncthreads();
    if (tid < NHEADS) {
        float s = 0.f;
        #pragma unroll
        for (int d = 0; d < HDIM; d++) s += sq[tid * HDIM + d];
        nrm[tid] = sqrtf(s) + 1e-6f;
    }
    __syncthreads();
    qn[tid] = qv / nrm[tid / HDIM] * 0.17677669529663687f;
    __syncthreads();
    int D = tid;
    #pragma unroll
    for (int h = 0; h < NHEADS; h++) {
        float s = 0.f;
        const float* wrow = Wk + D * HIDCH + h * HDIM;
        #pragma unroll
        for (int d = 0; d < HDIM; d++) s += qn[h * HDIM + d] * wrow[d];
        g_qWk[D * NHEADS + h] = s;
    }
    if (tid < NHEADS) {
        float s = 0.f;
        #pragma unroll
        for (int d = 0; d < HDIM; d++) s += Wkb[tid * HDIM + d] * qn[tid * HDIM + d];
        g_qb[tid] = s;
    }
}

// ============================================================
// Weight split: W fp32 -> hi/lo fp16 planes (hi+lo exact to 2^-22)
// ============================================================
__global__ void wsplit_kernel(const float* __restrict__ W,
                              __half* __restrict__ hi,
                              __half* __restrict__ lo) {
    int base = (blockIdx.x * 256 + threadIdx.x) * 8;
    float4 v0 = *(const float4*)(W + base);
    float4 v1 = *(const float4*)(W + base + 4);
    float v[8] = {v0.x, v0.y, v0.z, v0.w, v1.x, v1.y, v1.z, v1.w};
    __half h[8], l[8];
    #pragma unroll
    for (int e = 0; e < 8; e++) split_f16(v[e], h[e], l[e]);
    *(uint4*)(hi + base) = *(uint4*)h;
    *(uint4*)(lo + base) = *(uint4*)l;
}

// ============================================================
// Fused: x -> fp16 plane  AND  cost_exp[b][h][w]
//   One streaming pass over x. Each thread owns 2 w columns.
// ============================================================
__global__ void __launch_bounds__(256) xsplit_cost_kernel(const float* __restrict__ x) {
    __shared__ float sW[CINCH * NHEADS];
    __shared__ float sb[NHEADS];
    int tid = threadIdx.x;
    for (int i = tid; i < CINCH * NHEADS; i += 256) sW[i] = g_qWk[i];
    if (tid < NHEADS) sb[tid] = g_qb[tid];
    __syncthreads();

    int b = blockIdx.y;
    int w = blockIdx.x * 512 + tid * 2;
    const float* xb = x + (size_t)b * CINCH * WIDTH + w;
    __half* xh = g_xh + (size_t)b * CINCH * WIDTH + w;

    float a0[NHEADS], a1[NHEADS];
    #pragma unroll
    for (int h = 0; h < NHEADS; h++) { a0[h] = sb[h]; a1[h] = sb[h]; }

    #pragma unroll 4
    for (int D = 0; D < CINCH; D++) {
        float2 v = *(const float2*)(xb + (size_t)D * WIDTH);
        __half2 hv;
        hv.x = __float2half_rn(v.x);
        hv.y = __float2half_rn(v.y);
        *(__half2*)(xh + (size_t)D * WIDTH) = hv;
        #pragma unroll
        for (int h = 0; h < NHEADS; h++) {
            a0[h] = fmaf(v.x, sW[D * NHEADS + h], a0[h]);
            a1[h] = fmaf(v.y, sW[D * NHEADS + h], a1[h]);
        }
    }
    #pragma unroll
    for (int h = 0; h < NHEADS; h++) {
        float* crow = g_costE + ((size_t)b * NHEADS + h) * WIDTH + w;
        crow[0] = expf(a0[h]);
        crow[1] = expf(a1[h]);
    }
}

// ============================================================
// Kernel 2: denominator conv -> reciprocal
// ============================================================
__global__ void __launch_bounds__(256) denom_kernel(const float* __restrict__ rpe) {
    __shared__ float s[256 + 32];
    __shared__ float rks[KSZ];
    int h = blockIdx.y;
    int b = blockIdx.z;
    int w0 = blockIdx.x * 256;
    int tid = threadIdx.x;
    if (tid < KSZ) rks[tid] = expf(rpe[h * KSZ + tid]);
    const float* crow = g_costE + ((size_t)b * NHEADS + h) * WIDTH;
    #pragma unroll
    for (int i = tid; i < 256 + 32; i += 256) {
        int g = w0 - PADW + i;
        s[i] = (g >= 0 && g < WIDTH) ? crow[g] : 0.f;
    }
    __syncthreads();
    float rkr[KSZ];
    #pragma unroll
    for (int k = 0; k < KSZ; k++) rkr[k] = rks[k];
    float sc = 0.f;
    #pragma unroll
    for (int k = 0; k < KSZ; k++) sc = fmaf(s[tid + k], rkr[k], sc);
    g_rinv[((size_t)b * NHEADS + h) * WIDTH + w0 + tid] = 1.0f / sc;
}

// ============================================================
// Kernel 3: 31-tap conv on vc * rinv -> single fp16 plane g_rh
// ============================================================
#define CTILE 1024
__global__ void __launch_bounds__(256) conv_kernel(const float* __restrict__ rpe) {
    __shared__ __align__(16) float s[CTILE + 36];
    __shared__ float rks[KSZ];
    int c = blockIdx.y;
    int h = c >> 5;
    int b = blockIdx.z;
    int w0 = blockIdx.x * CTILE;
    int tid = threadIdx.x;
    if (tid < KSZ) rks[tid] = expf(rpe[h * KSZ + tid]);

    const float* vrow = g_vc + ((size_t)b * HIDCH + c) * WIDTH;
    #pragma unroll
    for (int i = tid; i < CTILE + 36; i += 256) {
        int g = w0 - PADW + i;
        s[i] = (g >= 0 && g < WIDTH) ? __ldg(vrow + g) : 0.f;
    }
    __syncthreads();

    float rkr[KSZ];
    #pragma unroll
    for (int k = 0; k < KSZ; k++) rkr[k] = rks[k];

    const int t4 = tid * 4;
    float a0 = 0.f, a1 = 0.f, a2 = 0.f, a3 = 0.f;
    #pragma unroll
    for (int u = 0; u < 9; u++) {
        float4 v4 = *(const float4*)&s[t4 + u * 4];
        float vv[4] = {v4.x, v4.y, v4.z, v4.w};
        #pragma unroll
        for (int e = 0; e < 4; e++) {
            const int m = u * 4 + e;
            if (m >= 0 && m < KSZ)         a0 = fmaf(vv[e], rkr[m],     a0);
            if (m - 1 >= 0 && m - 1 < KSZ) a1 = fmaf(vv[e], rkr[m - 1], a1);
            if (m - 2 >= 0 && m - 2 < KSZ) a2 = fmaf(vv[e], rkr[m - 2], a2);
            if (m - 3 >= 0 && m - 3 < KSZ) a3 = fmaf(vv[e], rkr[m - 3], a3);
        }
    }
    const float* rinv = g_rinv + ((size_t)b * NHEADS + h) * WIDTH + w0 + t4;
    float4 ri = *(const float4*)rinv;
    __half o[4];
    o[0] = __float2half_rn(a0 * ri.x);
    o[1] = __float2half_rn(a1 * ri.y);
    o[2] = __float2half_rn(a2 * ri.z);
    o[3] = __float2half_rn(a3 * ri.w);
    size_t obase = ((size_t)b * HIDCH + c) * WIDTH + w0 + t4;
    *(uint2*)(g_rh + obase) = *(uint2*)o;
}

// ============================================================
// HMMA fp16 2-term GEMM (cp.async pipelined)
//   C[c][w] = sum_k W[c][k] * X[k][w]
//   A = W hi/lo fp16 [c][k] (ldmatrix.x4)
//   B = X fp16 single plane [k][w] (ldmatrix.x2.trans)
//   D += Ahi*B + Alo*B     (W exact; error = A * resid(X) ~ 2^-11)
// ============================================================
#define SA_STRIDE 80     // bytes per A row (32 fp16 + 16B pad)
#define SB_STRIDE 272    // bytes per B k-row (128 fp16 + 16B pad)
#define OFF_AHI 0
#define OFF_ALO 10240
#define OFF_B   20480
#define STG_SZ  29184    // 20480 + 32*272
#define SM_STG  1024
#define SM_TOT_MMA (SM_STG + 2 * STG_SZ)   // 59392

template <int MODE>
__global__ void __launch_bounds__(256, 2)
gemm_mma(const float* __restrict__ bias, float* __restrict__ Out) {
    extern __shared__ __align__(16) char smem[];
    const uint32_t sbu = smem_to_u32(smem);
    float* sbias = (float*)smem;

    const int tid  = threadIdx.x;
    const int wid  = tid >> 5;
    const int lane = tid & 31;
    const int warp_m = wid >> 2;
    const int warp_n = wid & 3;
    const int bn = blockIdx.x * 128;   // w base
    const int cm = blockIdx.y * 128;   // c base
    const int b  = blockIdx.z;

    const __half* Whi = (MODE == 0) ? g_wvhi : g_wohi;
    const __half* Wlo = (MODE == 0) ? g_wvlo : g_wolo;
    const __half* Xh  = ((MODE == 0) ? g_xh : g_rh) + (size_t)b * CINCH * WIDTH;

    if (tid < 128) sbias[tid] = bias[cm + tid];

    const int av0 = tid * 2;
    auto issue = [&](int chunk, int slot) {
        const uint32_t stgu = sbu + SM_STG + slot * STG_SZ;
        const int k0 = chunk * 32;
        #pragma unroll
        for (int j = 0; j < 2; j++) {
            int v = av0 + j;
            int r = v >> 2, c4 = v & 3;
            const __half* sh = Whi + (size_t)(cm + r) * CINCH + k0 + c4 * 8;
            const __half* sl = Wlo + (size_t)(cm + r) * CINCH + k0 + c4 * 8;
            cp_async16(stgu + OFF_AHI + r * SA_STRIDE + c4 * 16, sh);
            cp_async16(stgu + OFF_ALO + r * SA_STRIDE + c4 * 16, sl);
        }
        #pragma unroll
        for (int j = 0; j < 2; j++) {
            int v = av0 + j;
            int r = v >> 4, c = v & 15;
            const __half* sx = Xh + (size_t)(k0 + r) * WIDTH + bn + c * 8;
            cp_async16(stgu + OFF_B + r * SB_STRIDE + c * 16, sx);
        }
        CP_COMMIT();
    };

    float d[4][4][4];
    #pragma unroll
    for (int mi = 0; mi < 4; mi++)
        #pragma unroll
        for (int ni = 0; ni < 4; ni++)
            #pragma unroll
            for (int e = 0; e < 4; e++) d[mi][ni][e] = 0.f;

    issue(0, 0);

    for (int i = 0; i < 8; i++) {
        if (i < 7) issue(i + 1, (i + 1) & 1);
        if (i < 7) { CP_WAIT(1); } else { CP_WAIT(0); }
        __syncthreads();

        const uint32_t stgb = sbu + SM_STG + (i & 1) * STG_SZ;
        #pragma unroll
        for (int ks = 0; ks < 2; ks++) {
            uint32_t ah[4][4], al[4][4];
            #pragma unroll
            for (int mi = 0; mi < 4; mi++) {
                uint32_t addr = stgb + OFF_AHI
                    + (uint32_t)(warp_m * 64 + mi * 16 + (lane & 15)) * SA_STRIDE
                    + ks * 32 + (lane >> 4) * 16;
                ldsm_x4(ah[mi], addr);
                ldsm_x4(al[mi], addr + (OFF_ALO - OFF_AHI));
            }
            #pragma unroll
            for (int ni = 0; ni < 4; ni++) {
                uint32_t addr = stgb + OFF_B
                    + (uint32_t)(ks * 16 + (lane & 15)) * SB_STRIDE
                    + (warp_n * 32 + ni * 8) * 2;
                uint32_t bh[2];
                ldsm_x2t(bh, addr);
                #pragma unroll
                for (int mi = 0; mi < 4; mi++) mma_f16(d[mi][ni], ah[mi], bh);
                #pragma unroll
                for (int mi = 0; mi < 4; mi++) mma_f16(d[mi][ni], al[mi], bh);
            }
        }
        __syncthreads();
    }

    // ---- epilogue ----
    #pragma unroll
    for (int mi = 0; mi < 4; mi++) {
        int cl0 = warp_m * 64 + mi * 16 + (lane >> 2);
        int c0 = cm + cl0;
        int h = c0 >> 5;
        float bv0 = sbias[cl0];
        float bv1 = sbias[cl0 + 8];
        #pragma unroll
        for (int ni = 0; ni < 4; ni++) {
            int w0 = bn + warp_n * 32 + ni * 8 + (lane & 3) * 2;
            float2 o0, o1;
            if (MODE == 0) {
                float2 ce = *(const float2*)&g_costE[((size_t)b * NHEADS + h) * WIDTH + w0];
                o0.x = ce.x * (d[mi][ni][0] + bv0);
                o0.y = ce.y * (d[mi][ni][1] + bv0);
                o1.x = ce.x * (d[mi][ni][2] + bv1);
                o1.y = ce.y * (d[mi][ni][3] + bv1);
                *(float2*)&g_vc[((size_t)b * HIDCH + c0) * WIDTH + w0]     = o0;
                *(float2*)&g_vc[((size_t)b * HIDCH + c0 + 8) * WIDTH + w0] = o1;
            } else {
                o0.x = d[mi][ni][0] + bv0;
                o0.y = d[mi][ni][1] + bv0;
                o1.x = d[mi][ni][2] + bv1;
                o1.y = d[mi][ni][3] + bv1;
                *(float2*)&Out[((size_t)b * HIDCH + c0) * WIDTH + w0]     = o0;
                *(float2*)&Out[((size_t)b * HIDCH + c0 + 8) * WIDTH + w0] = o1;
            }
        }
    }
}

// ============================================================
extern "C" void kernel_launch(void* const* d_in, const int* in_sizes, int n_in,
                              void* d_out, int out_size) {
    const float* x     = (const float*)d_in[0];
    const float* query = (const float*)d_in[1];
    const float* Wk    = (const float*)d_in[2];
    const float* Wkb   = (const float*)d_in[3];
    const float* rpe   = (const float*)d_in[4];
    const float* Wv    = (const float*)d_in[5];
    const float* bv    = (const float*)d_in[6];
    const float* Wo    = (const float*)d_in[7];
    const float* bo    = (const float*)d_in[8];
    float* out = (float*)d_out;

    cudaFuncSetAttribute(gemm_mma<0>, cudaFuncAttributeMaxDynamicSharedMemorySize, SM_TOT_MMA);
    cudaFuncSetAttribute(gemm_mma<1>, cudaFuncAttributeMaxDynamicSharedMemorySize, SM_TOT_MMA);

    precompute_kernel<<<1, 256>>>(query, Wk, Wkb);
    {
        __half *dvh, *dvl, *doh, *dol;
        cudaGetSymbolAddress((void**)&dvh, g_wvhi);
        cudaGetSymbolAddress((void**)&dvl, g_wvlo);
        cudaGetSymbolAddress((void**)&doh, g_wohi);
        cudaGetSymbolAddress((void**)&dol, g_wolo);
        wsplit_kernel<<<32, 256>>>(Wv, dvh, dvl);
        wsplit_kernel<<<32, 256>>>(Wo, doh, dol);
    }
    xsplit_cost_kernel<<<dim3(WIDTH / 512, BATCH), 256>>>(x);
    denom_kernel<<<dim3(WIDTH / 256, NHEADS, BATCH), 256>>>(rpe);
    gemm_mma<0><<<dim3(WIDTH / 128, HIDCH / 128, BATCH), 256, SM_TOT_MMA>>>(bv, nullptr);
    conv_kernel<<<dim3(WIDTH / CTILE, HIDCH, BATCH), 256>>>(rpe);
    gemm_mma<1><<<dim3(WIDTH / 128, HIDCH / 128, BATCH), 256, SM_TOT_MMA>>>(bo, out);
}

// round 10
// speedup vs baseline: 2.3752x; 1.0454x over previous
#include <cuda_runtime.h>
#include <cuda_fp16.h>
#include <cstdint>
#include <math.h>

#define BATCH  8
#define CINCH  256
#define HIDCH  256
#define NHEADS 8
#define HDIM   32
#define KSZ    31
#define PADW   15
#define WIDTH  16384

// ---- scratch (device globals; no allocation allowed) ----
__device__ float g_qWk[CINCH * NHEADS];
__device__ float g_qb[NHEADS];
__device__ float g_costE[BATCH * NHEADS * WIDTH];                 // 4 MB
__device__ float g_rinv [BATCH * NHEADS * WIDTH];                 // 4 MB
__device__ float g_vc[(size_t)BATCH * HIDCH * WIDTH];             // 128 MB
__device__ __half g_xh[(size_t)BATCH * CINCH * WIDTH];            // 64 MB
__device__ __half g_rh[(size_t)BATCH * HIDCH * WIDTH];            // 64 MB
__device__ __half g_wvhi[HIDCH * CINCH];
__device__ __half g_wvlo[HIDCH * CINCH];
__device__ __half g_wohi[HIDCH * HIDCH];
__device__ __half g_wolo[HIDCH * HIDCH];

// ============================================================
// helpers
// ============================================================
__device__ __forceinline__ uint32_t smem_to_u32(const void* p) {
    uint32_t a;
    asm("{ .reg .u64 t; cvta.to.shared.u64 t, %1; cvt.u32.u64 %0, t; }" : "=r"(a) : "l"(p));
    return a;
}
__device__ __forceinline__ void ldsm_x4(uint32_t* r, uint32_t addr) {
    asm volatile("ldmatrix.sync.aligned.m8n8.x4.shared.b16 {%0,%1,%2,%3}, [%4];"
                 : "=r"(r[0]), "=r"(r[1]), "=r"(r[2]), "=r"(r[3]) : "r"(addr));
}
__device__ __forceinline__ void ldsm_x2t(uint32_t* r, uint32_t addr) {
    asm volatile("ldmatrix.sync.aligned.m8n8.x2.trans.shared.b16 {%0,%1}, [%2];"
                 : "=r"(r[0]), "=r"(r[1]) : "r"(addr));
}
__device__ __forceinline__ void mma_f16(float* d, const uint32_t* a, const uint32_t* b) {
    asm volatile("mma.sync.aligned.m16n8k16.row.col.f32.f16.f16.f32 "
                 "{%0,%1,%2,%3}, {%4,%5,%6,%7}, {%8,%9}, {%0,%1,%2,%3};"
                 : "+f"(d[0]), "+f"(d[1]), "+f"(d[2]), "+f"(d[3])
                 : "r"(a[0]), "r"(a[1]), "r"(a[2]), "r"(a[3]),
                   "r"(b[0]), "r"(b[1]));
}
__device__ __forceinline__ void split_f16(float v, __half& hi, __half& lo) {
    hi = __float2half_rn(v);
    lo = __float2half_rn(v - __half2float(hi));
}
__device__ __forceinline__ void cp_async16(uint32_t dst, const void* src) {
    asm volatile("cp.async.cg.shared.global [%0], [%1], 16;" :: "r"(dst), "l"(src));
}
#define CP_COMMIT() asm volatile("cp.async.commit_group;" ::: "memory")
#define CP_WAIT(n)  asm volatile("cp.async.wait_group %0;" :: "n"(n) : "memory")

// ============================================================
// Kernel 0: precompute qWk[D][h], qb[h]
// ============================================================
__global__ void precompute_kernel(const float* __restrict__ query,
                                  const float* __restrict__ Wk,
                                  const float* __restrict__ Wkb) {
    __shared__ float sq[CINCH];
    __shared__ float qn[CINCH];
    __shared__ float nrm[NHEADS];
    int tid = threadIdx.x;
    float qv = query[tid];
    sq[tid] = qv * qv;
    __syncthreads();
    if (tid < NHEADS) {
        float s = 0.f;
        #pragma unroll
        for (int d = 0; d < HDIM; d++) s += sq[tid * HDIM + d];
        nrm[tid] = sqrtf(s) + 1e-6f;
    }
    __syncthreads();
    qn[tid] = qv / nrm[tid / HDIM] * 0.17677669529663687f;
    __syncthreads();
    int D = tid;
    #pragma unroll
    for (int h = 0; h < NHEADS; h++) {
        float s = 0.f;
        const float* wrow = Wk + D * HIDCH + h * HDIM;
        #pragma unroll
        for (int d = 0; d < HDIM; d++) s += qn[h * HDIM + d] * wrow[d];
        g_qWk[D * NHEADS + h] = s;
    }
    if (tid < NHEADS) {
        float s = 0.f;
        #pragma unroll
        for (int d = 0; d < HDIM; d++) s += Wkb[tid * HDIM + d] * qn[tid * HDIM + d];
        g_qb[tid] = s;
    }
}

// ============================================================
// Weight split: W fp32 -> hi/lo fp16 planes (hi+lo exact to 2^-22)
// ============================================================
__global__ void wsplit_kernel(const float* __restrict__ W,
                              __half* __restrict__ hi,
                              __half* __restrict__ lo) {
    int base = (blockIdx.x * 256 + threadIdx.x) * 8;
    float4 v0 = *(const float4*)(W + base);
    float4 v1 = *(const float4*)(W + base + 4);
    float v[8] = {v0.x, v0.y, v0.z, v0.w, v1.x, v1.y, v1.z, v1.w};
    __half h[8], l[8];
    #pragma unroll
    for (int e = 0; e < 8; e++) split_f16(v[e], h[e], l[e]);
    *(uint4*)(hi + base) = *(uint4*)h;
    *(uint4*)(lo + base) = *(uint4*)l;
}

// ============================================================
// Fused: x -> fp16 plane  AND  cost_exp[b][h][w]
//   One streaming pass; 1 w-column per thread, 512 blocks.
// ============================================================
__global__ void __launch_bounds__(256) xsplit_cost_kernel(const float* __restrict__ x) {
    __shared__ float sW[CINCH * NHEADS];
    __shared__ float sb[NHEADS];
    int tid = threadIdx.x;
    for (int i = tid; i < CINCH * NHEADS; i += 256) sW[i] = g_qWk[i];
    if (tid < NHEADS) sb[tid] = g_qb[tid];
    __syncthreads();

    int b = blockIdx.y;
    int w = blockIdx.x * 256 + tid;
    const float* xb = x + (size_t)b * CINCH * WIDTH + w;
    __half* xh = g_xh + (size_t)b * CINCH * WIDTH + w;

    float acc[NHEADS];
    #pragma unroll
    for (int h = 0; h < NHEADS; h++) acc[h] = sb[h];

    #pragma unroll 4
    for (int D = 0; D < CINCH; D++) {
        float v = __ldg(xb + (size_t)D * WIDTH);
        xh[(size_t)D * WIDTH] = __float2half_rn(v);
        #pragma unroll
        for (int h = 0; h < NHEADS; h++)
            acc[h] = fmaf(v, sW[D * NHEADS + h], acc[h]);
    }
    #pragma unroll
    for (int h = 0; h < NHEADS; h++)
        g_costE[((size_t)b * NHEADS + h) * WIDTH + w] = expf(acc[h]);
}

// ============================================================
// Kernel 2: denominator conv -> reciprocal
// ============================================================
__global__ void __launch_bounds__(256) denom_kernel(const float* __restrict__ rpe) {
    __shared__ float s[256 + 32];
    __shared__ float rks[KSZ];
    int h = blockIdx.y;
    int b = blockIdx.z;
    int w0 = blockIdx.x * 256;
    int tid = threadIdx.x;
    if (tid < KSZ) rks[tid] = expf(rpe[h * KSZ + tid]);
    const float* crow = g_costE + ((size_t)b * NHEADS + h) * WIDTH;
    #pragma unroll
    for (int i = tid; i < 256 + 32; i += 256) {
        int g = w0 - PADW + i;
        s[i] = (g >= 0 && g < WIDTH) ? crow[g] : 0.f;
    }
    __syncthreads();
    float rkr[KSZ];
    #pragma unroll
    for (int k = 0; k < KSZ; k++) rkr[k] = rks[k];
    float sc = 0.f;
    #pragma unroll
    for (int k = 0; k < KSZ; k++) sc = fmaf(s[tid + k], rkr[k], sc);
    g_rinv[((size_t)b * NHEADS + h) * WIDTH + w0 + tid] = 1.0f / sc;
}

// ============================================================
// Kernel 3: 31-tap conv on vc * rinv -> fp16 plane g_rh
//   CTILE=2048, 8 outputs/thread (248 unrolled FMA).
// ============================================================
#define CTILE 2048
__global__ void __launch_bounds__(256) conv_kernel(const float* __restrict__ rpe) {
    __shared__ __align__(16) float s[CTILE + 40];
    __shared__ float rks[KSZ];
    int c = blockIdx.y;
    int h = c >> 5;
    int b = blockIdx.z;
    int w0 = blockIdx.x * CTILE;
    int tid = threadIdx.x;
    if (tid < KSZ) rks[tid] = expf(rpe[h * KSZ + tid]);

    const float* vrow = g_vc + ((size_t)b * HIDCH + c) * WIDTH;
    #pragma unroll
    for (int i = tid; i < CTILE + 36; i += 256) {
        int g = w0 - PADW + i;
        s[i] = (g >= 0 && g < WIDTH) ? __ldg(vrow + g) : 0.f;
    }
    __syncthreads();

    float rkr[KSZ];
    #pragma unroll
    for (int k = 0; k < KSZ; k++) rkr[k] = rks[k];

    const int t8 = tid * 8;
    float a[8];
    #pragma unroll
    for (int o = 0; o < 8; o++) a[o] = 0.f;

    #pragma unroll
    for (int u = 0; u < 10; u++) {
        float4 v4 = *(const float4*)&s[t8 + u * 4];
        float vv[4] = {v4.x, v4.y, v4.z, v4.w};
        #pragma unroll
        for (int e = 0; e < 4; e++) {
            const int m = u * 4 + e;
            #pragma unroll
            for (int o = 0; o < 8; o++) {
                const int k = m - o;
                if (k >= 0 && k < KSZ) a[o] = fmaf(vv[e], rkr[k], a[o]);
            }
        }
    }
    const float* rinv = g_rinv + ((size_t)b * NHEADS + h) * WIDTH + w0 + t8;
    float4 r0 = *(const float4*)rinv;
    float4 r1 = *(const float4*)(rinv + 4);
    __half o16[8];
    o16[0] = __float2half_rn(a[0] * r0.x);
    o16[1] = __float2half_rn(a[1] * r0.y);
    o16[2] = __float2half_rn(a[2] * r0.z);
    o16[3] = __float2half_rn(a[3] * r0.w);
    o16[4] = __float2half_rn(a[4] * r1.x);
    o16[5] = __float2half_rn(a[5] * r1.y);
    o16[6] = __float2half_rn(a[6] * r1.z);
    o16[7] = __float2half_rn(a[7] * r1.w);
    size_t obase = ((size_t)b * HIDCH + c) * WIDTH + w0 + t8;
    *(uint4*)(g_rh + obase) = *(uint4*)o16;
}

// ============================================================
// HMMA fp16 2-term GEMM, 3-stage cp.async pipeline
//   C[c][w] = sum_k W[c][k] * X[k][w]
//   A = W hi/lo fp16 [c][k] (ldmatrix.x4)
//   B = X fp16 [k][w] (ldmatrix.x2.trans)
//   D += Ahi*B + Alo*B
// ============================================================
#define SA_STRIDE 80     // bytes per A row (32 fp16 + 16B pad)
#define SB_STRIDE 272    // bytes per B k-row (128 fp16 + 16B pad)
#define OFF_AHI 0
#define OFF_ALO 10240
#define OFF_B   20480
#define STG_SZ  29184    // 20480 + 32*272
#define SM_STG  1024
#define SM_TOT_MMA (SM_STG + 3 * STG_SZ)   // 88576

template <int MODE>
__global__ void __launch_bounds__(256, 2)
gemm_mma(const float* __restrict__ bias, float* __restrict__ Out) {
    extern __shared__ __align__(16) char smem[];
    const uint32_t sbu = smem_to_u32(smem);
    float* sbias = (float*)smem;

    const int tid  = threadIdx.x;
    const int wid  = tid >> 5;
    const int lane = tid & 31;
    const int warp_m = wid >> 2;
    const int warp_n = wid & 3;
    const int bn = blockIdx.x * 128;   // w base
    const int cm = blockIdx.y * 128;   // c base
    const int b  = blockIdx.z;

    const __half* Whi = (MODE == 0) ? g_wvhi : g_wohi;
    const __half* Wlo = (MODE == 0) ? g_wvlo : g_wolo;
    const __half* Xh  = ((MODE == 0) ? g_xh : g_rh) + (size_t)b * CINCH * WIDTH;

    if (tid < 128) sbias[tid] = bias[cm + tid];

    const int av0 = tid * 2;
    auto issue = [&](int chunk, int slot) {
        const uint32_t stgu = sbu + SM_STG + slot * STG_SZ;
        const int k0 = chunk * 32;
        #pragma unroll
        for (int j = 0; j < 2; j++) {
            int v = av0 + j;
            int r = v >> 2, c4 = v & 3;
            const __half* sh = Whi + (size_t)(cm + r) * CINCH + k0 + c4 * 8;
            const __half* sl = Wlo + (size_t)(cm + r) * CINCH + k0 + c4 * 8;
            cp_async16(stgu + OFF_AHI + r * SA_STRIDE + c4 * 16, sh);
            cp_async16(stgu + OFF_ALO + r * SA_STRIDE + c4 * 16, sl);
        }
        #pragma unroll
        for (int j = 0; j < 2; j++) {
            int v = av0 + j;
            int r = v >> 4, c = v & 15;
            const __half* sx = Xh + (size_t)(k0 + r) * WIDTH + bn + c * 8;
            cp_async16(stgu + OFF_B + r * SB_STRIDE + c * 16, sx);
        }
        CP_COMMIT();
    };

    float d[4][4][4];
    #pragma unroll
    for (int mi = 0; mi < 4; mi++)
        #pragma unroll
        for (int ni = 0; ni < 4; ni++)
            #pragma unroll
            for (int e = 0; e < 4; e++) d[mi][ni][e] = 0.f;

    issue(0, 0);
    issue(1, 1);

    for (int i = 0; i < 8; i++) {
        CP_WAIT(1);          // chunk i landed (chunk i+1 may be in flight)
        __syncthreads();     // smem visible; all warps done with chunk i-1's slot
        if (i < 6) issue(i + 2, (i + 2) % 3);

        const uint32_t stgb = sbu + SM_STG + (i % 3) * STG_SZ;
        #pragma unroll
        for (int ks = 0; ks < 2; ks++) {
            uint32_t ah[4][4], al[4][4];
            #pragma unroll
            for (int mi = 0; mi < 4; mi++) {
                uint32_t addr = stgb + OFF_AHI
                    + (uint32_t)(warp_m * 64 + mi * 16 + (lane & 15)) * SA_STRIDE
                    + ks * 32 + (lane >> 4) * 16;
                ldsm_x4(ah[mi], addr);
                ldsm_x4(al[mi], addr + (OFF_ALO - OFF_AHI));
            }
            #pragma unroll
            for (int ni = 0; ni < 4; ni++) {
                uint32_t addr = stgb + OFF_B
                    + (uint32_t)(ks * 16 + (lane & 15)) * SB_STRIDE
                    + (warp_n * 32 + ni * 8) * 2;
                uint32_t bh[2];
                ldsm_x2t(bh, addr);
                #pragma unroll
                for (int mi = 0; mi < 4; mi++) mma_f16(d[mi][ni], ah[mi], bh);
                #pragma unroll
                for (int mi = 0; mi < 4; mi++) mma_f16(d[mi][ni], al[mi], bh);
            }
        }
    }

    // ---- epilogue ----
    #pragma unroll
    for (int mi = 0; mi < 4; mi++) {
        int cl0 = warp_m * 64 + mi * 16 + (lane >> 2);
        int c0 = cm + cl0;
        int h = c0 >> 5;
        float bv0 = sbias[cl0];
        float bv1 = sbias[cl0 + 8];
        #pragma unroll
        for (int ni = 0; ni < 4; ni++) {
            int w0 = bn + warp_n * 32 + ni * 8 + (lane & 3) * 2;
            float2 o0, o1;
            if (MODE == 0) {
                float2 ce = *(const float2*)&g_costE[((size_t)b * NHEADS + h) * WIDTH + w0];
                o0.x = ce.x * (d[mi][ni][0] + bv0);
                o0.y = ce.y * (d[mi][ni][1] + bv0);
                o1.x = ce.x * (d[mi][ni][2] + bv1);
                o1.y = ce.y * (d[mi][ni][3] + bv1);
                *(float2*)&g_vc[((size_t)b * HIDCH + c0) * WIDTH + w0]     = o0;
                *(float2*)&g_vc[((size_t)b * HIDCH + c0 + 8) * WIDTH + w0] = o1;
            } else {
                o0.x = d[mi][ni][0] + bv0;
                o0.y = d[mi][ni][1] + bv0;
                o1.x = d[mi][ni][2] + bv1;
                o1.y = d[mi][ni][3] + bv1;
                *(float2*)&Out[((size_t)b * HIDCH + c0) * WIDTH + w0]     = o0;
                *(float2*)&Out[((size_t)b * HIDCH + c0 + 8) * WIDTH + w0] = o1;
            }
        }
    }
}

// ============================================================
extern "C" void kernel_launch(void* const* d_in, const int* in_sizes, int n_in,
                              void* d_out, int out_size) {
    const float* x     = (const float*)d_in[0];
    const float* query = (const float*)d_in[1];
    const float* Wk    = (const float*)d_in[2];
    const float* Wkb   = (const float*)d_in[3];
    const float* rpe   = (const float*)d_in[4];
    const float* Wv    = (const float*)d_in[5];
    const float* bv    = (const float*)d_in[6];
    const float* Wo    = (const float*)d_in[7];
    const float* bo    = (const float*)d_in[8];
    float* out = (float*)d_out;

    cudaFuncSetAttribute(gemm_mma<0>, cudaFuncAttributeMaxDynamicSharedMemorySize, SM_TOT_MMA);
    cudaFuncSetAttribute(gemm_mma<1>, cudaFuncAttributeMaxDynamicSharedMemorySize, SM_TOT_MMA);

    precompute_kernel<<<1, 256>>>(query, Wk, Wkb);
    {
        __half *dvh, *dvl, *doh, *dol;
        cudaGetSymbolAddress((void**)&dvh, g_wvhi);
        cudaGetSymbolAddress((void**)&dvl, g_wvlo);
        cudaGetSymbolAddress((void**)&doh, g_wohi);
        cudaGetSymbolAddress((void**)&dol, g_wolo);
        wsplit_kernel<<<32, 256>>>(Wv, dvh, dvl);
        wsplit_kernel<<<32, 256>>>(Wo, doh, dol);
    }
    xsplit_cost_kernel<<<dim3(WIDTH / 256, BATCH), 256>>>(x);
    denom_kernel<<<dim3(WIDTH / 256, NHEADS, BATCH), 256>>>(rpe);
    gemm_mma<0><<<dim3(WIDTH / 128, HIDCH / 128, BATCH), 256, SM_TOT_MMA>>>(bv, nullptr);
    conv_kernel<<<dim3(WIDTH / CTILE, HIDCH, BATCH), 256>>>(rpe);
    gemm_mma<1><<<dim3(WIDTH / 128, HIDCH / 128, BATCH), 256, SM_TOT_MMA>>>(bo, out);
}

// round 13
// speedup vs baseline: 2.4129x; 1.0159x over previous
#include <cuda_runtime.h>
#include <cuda_fp16.h>
#include <cstdint>
#include <math.h>

#define BATCH  8
#define CINCH  256
#define HIDCH  256
#define NHEADS 8
#define HDIM   32
#define KSZ    31
#define PADW   15
#define WIDTH  16384

// ---- scratch (device globals; no allocation allowed) ----
__device__ float g_qWk[CINCH * NHEADS];
__device__ float g_qb[NHEADS];
__device__ float g_costE[BATCH * NHEADS * WIDTH];                 // 4 MB (L2-resident)
__device__ float g_rinv [BATCH * NHEADS * WIDTH];                 // 4 MB
__device__ __half g_vh[(size_t)BATCH * HIDCH * WIDTH];            // 64 MB (v, pre-cost)
__device__ __half g_xh[(size_t)BATCH * CINCH * WIDTH];            // 64 MB
__device__ __half g_rh[(size_t)BATCH * HIDCH * WIDTH];            // 64 MB
__device__ __half g_wvhi[HIDCH * CINCH];
__device__ __half g_wvlo[HIDCH * CINCH];
__device__ __half g_wohi[HIDCH * HIDCH];
__device__ __half g_wolo[HIDCH * HIDCH];

// ============================================================
// helpers
// ============================================================
__device__ __forceinline__ uint32_t smem_to_u32(const void* p) {
    uint32_t a;
    asm("{ .reg .u64 t; cvta.to.shared.u64 t, %1; cvt.u32.u64 %0, t; }" : "=r"(a) : "l"(p));
    return a;
}
__device__ __forceinline__ void ldsm_x4(uint32_t* r, uint32_t addr) {
    asm volatile("ldmatrix.sync.aligned.m8n8.x4.shared.b16 {%0,%1,%2,%3}, [%4];"
                 : "=r"(r[0]), "=r"(r[1]), "=r"(r[2]), "=r"(r[3]) : "r"(addr));
}
__device__ __forceinline__ void ldsm_x2t(uint32_t* r, uint32_t addr) {
    asm volatile("ldmatrix.sync.aligned.m8n8.x2.trans.shared.b16 {%0,%1}, [%2];"
                 : "=r"(r[0]), "=r"(r[1]) : "r"(addr));
}
__device__ __forceinline__ void mma_f16(float* d, const uint32_t* a, const uint32_t* b) {
    asm volatile("mma.sync.aligned.m16n8k16.row.col.f32.f16.f16.f32 "
                 "{%0,%1,%2,%3}, {%4,%5,%6,%7}, {%8,%9}, {%0,%1,%2,%3};"
                 : "+f"(d[0]), "+f"(d[1]), "+f"(d[2]), "+f"(d[3])
                 : "r"(a[0]), "r"(a[1]), "r"(a[2]), "r"(a[3]),
                   "r"(b[0]), "r"(b[1]));
}
__device__ __forceinline__ void split_f16(float v, __half& hi, __half& lo) {
    hi = __float2half_rn(v);
    lo = __float2half_rn(v - __half2float(hi));
}
__device__ __forceinline__ void cp_async16(uint32_t dst, const void* src) {
    asm volatile("cp.async.cg.shared.global [%0], [%1], 16;" :: "r"(dst), "l"(src));
}
#define CP_COMMIT() asm volatile("cp.async.commit_group;" ::: "memory")
#define CP_WAIT(n)  asm volatile("cp.async.wait_group %0;" :: "n"(n) : "memory")

// ============================================================
// Kernel 0: precompute qWk[D][h], qb[h]
// ============================================================
__global__ void precompute_kernel(const float* __restrict__ query,
                                  const float* __restrict__ Wk,
                                  const float* __restrict__ Wkb) {
    __shared__ float sq[CINCH];
    __shared__ float qn[CINCH];
    __shared__ float nrm[NHEADS];
    int tid = threadIdx.x;
    float qv = query[tid];
    sq[tid] = qv * qv;
    __syncthreads();
    if (tid < NHEADS) {
        float s = 0.f;
        #pragma unroll
        for (int d = 0; d < HDIM; d++) s += sq[tid * HDIM + d];
        nrm[tid] = sqrtf(s) + 1e-6f;
    }
    __syncthreads();
    qn[tid] = qv / nrm[tid / HDIM] * 0.17677669529663687f;
    __syncthreads();
    int D = tid;
    #pragma unroll
    for (int h = 0; h < NHEADS; h++) {
        float s = 0.f;
        const float* wrow = Wk + D * HIDCH + h * HDIM;
        #pragma unroll
        for (int d = 0; d < HDIM; d++) s += qn[h * HDIM + d] * wrow[d];
        g_qWk[D * NHEADS + h] = s;
    }
    if (tid < NHEADS) {
        float s = 0.f;
        #pragma unroll
        for (int d = 0; d < HDIM; d++) s += Wkb[tid * HDIM + d] * qn[tid * HDIM + d];
        g_qb[tid] = s;
    }
}

// ============================================================
// Weight split: W fp32 -> hi/lo fp16 planes (hi+lo exact to 2^-22)
// ============================================================
__global__ void wsplit_kernel(const float* __restrict__ W,
                              __half* __restrict__ hi,
                              __half* __restrict__ lo) {
    int base = (blockIdx.x * 256 + threadIdx.x) * 8;
    float4 v0 = *(const float4*)(W + base);
    float4 v1 = *(const float4*)(W + base + 4);
    float v[8] = {v0.x, v0.y, v0.z, v0.w, v1.x, v1.y, v1.z, v1.w};
    __half h[8], l[8];
    #pragma unroll
    for (int e = 0; e < 8; e++) split_f16(v[e], h[e], l[e]);
    *(uint4*)(hi + base) = *(uint4*)h;
    *(uint4*)(lo + base) = *(uint4*)l;
}

// ============================================================
// Fused: x -> fp16 plane  AND  cost_exp[b][h][w]
// ============================================================
__global__ void __launch_bounds__(256) xsplit_cost_kernel(const float* __restrict__ x) {
    __shared__ float sW[CINCH * NHEADS];
    __shared__ float sb[NHEADS];
    int tid = threadIdx.x;
    for (int i = tid; i < CINCH * NHEADS; i += 256) sW[i] = g_qWk[i];
    if (tid < NHEADS) sb[tid] = g_qb[tid];
    __syncthreads();

    int b = blockIdx.y;
    int w = blockIdx.x * 256 + tid;
    const float* xb = x + (size_t)b * CINCH * WIDTH + w;
    __half* xh = g_xh + (size_t)b * CINCH * WIDTH + w;

    float acc[NHEADS];
    #pragma unroll
    for (int h = 0; h < NHEADS; h++) acc[h] = sb[h];

    #pragma unroll 8
    for (int D = 0; D < CINCH; D++) {
        float v = __ldg(xb + (size_t)D * WIDTH);
        xh[(size_t)D * WIDTH] = __float2half_rn(v);
        #pragma unroll
        for (int h = 0; h < NHEADS; h++)
            acc[h] = fmaf(v, sW[D * NHEADS + h], acc[h]);
    }
    #pragma unroll
    for (int h = 0; h < NHEADS; h++)
        g_costE[((size_t)b * NHEADS + h) * WIDTH + w] = expf(acc[h]);
}

// ============================================================
// Kernel 2: denominator conv -> reciprocal
// ============================================================
__global__ void __launch_bounds__(256) denom_kernel(const float* __restrict__ rpe) {
    __shared__ float s[256 + 32];
    __shared__ float rks[KSZ];
    int h = blockIdx.y;
    int b = blockIdx.z;
    int w0 = blockIdx.x * 256;
    int tid = threadIdx.x;
    if (tid < KSZ) rks[tid] = expf(rpe[h * KSZ + tid]);
    const float* crow = g_costE + ((size_t)b * NHEADS + h) * WIDTH;
    #pragma unroll
    for (int i = tid; i < 256 + 32; i += 256) {
        int g = w0 - PADW + i;
        s[i] = (g >= 0 && g < WIDTH) ? crow[g] : 0.f;
    }
    __syncthreads();
    float rkr[KSZ];
    #pragma unroll
    for (int k = 0; k < KSZ; k++) rkr[k] = rks[k];
    float sc = 0.f;
    #pragma unroll
    for (int k = 0; k < KSZ; k++) sc = fmaf(s[tid + k], rkr[k], sc);
    g_rinv[((size_t)b * NHEADS + h) * WIDTH + w0 + tid] = 1.0f / sc;
}

// ============================================================
// Kernel 3: conv on p = cE * v  (v fp16, cE fp32 L2-hot), * rinv -> g_rh
//   CTILE=2048, 8 outputs/thread.
// ============================================================
#define CTILE 2048
__global__ void __launch_bounds__(256) conv_kernel(const float* __restrict__ rpe) {
    __shared__ __align__(16) float s[CTILE + 40];
    __shared__ float rks[KSZ];
    int c = blockIdx.y;
    int h = c >> 5;
    int b = blockIdx.z;
    int w0 = blockIdx.x * CTILE;
    int tid = threadIdx.x;
    if (tid < KSZ) rks[tid] = expf(rpe[h * KSZ + tid]);

    const __half* vrow = g_vh + ((size_t)b * HIDCH + c) * WIDTH;
    const float* crow = g_costE + ((size_t)b * NHEADS + h) * WIDTH;
    #pragma unroll
    for (int i = tid; i < CTILE + 36; i += 256) {
        int g = w0 - PADW + i;
        s[i] = (g >= 0 && g < WIDTH)
             ? __half2float(__ldg(vrow + g)) * __ldg(crow + g) : 0.f;
    }
    __syncthreads();

    float rkr[KSZ];
    #pragma unroll
    for (int k = 0; k < KSZ; k++) rkr[k] = rks[k];

    const int t8 = tid * 8;
    float a[8];
    #pragma unroll
    for (int o = 0; o < 8; o++) a[o] = 0.f;

    #pragma unroll
    for (int u = 0; u < 10; u++) {
        float4 v4 = *(const float4*)&s[t8 + u * 4];
        float vv[4] = {v4.x, v4.y, v4.z, v4.w};
        #pragma unroll
        for (int e = 0; e < 4; e++) {
            const int m = u * 4 + e;
            #pragma unroll
            for (int o = 0; o < 8; o++) {
                const int k = m - o;
                if (k >= 0 && k < KSZ) a[o] = fmaf(vv[e], rkr[k], a[o]);
            }
        }
    }
    const float* rinv = g_rinv + ((size_t)b * NHEADS + h) * WIDTH + w0 + t8;
    float4 r0 = *(const float4*)rinv;
    float4 r1 = *(const float4*)(rinv + 4);
    __half o16[8];
    o16[0] = __float2half_rn(a[0] * r0.x);
    o16[1] = __float2half_rn(a[1] * r0.y);
    o16[2] = __float2half_rn(a[2] * r0.z);
    o16[3] = __float2half_rn(a[3] * r0.w);
    o16[4] = __float2half_rn(a[4] * r1.x);
    o16[5] = __float2half_rn(a[5] * r1.y);
    o16[6] = __float2half_rn(a[6] * r1.z);
    o16[7] = __float2half_rn(a[7] * r1.w);
    size_t obase = ((size_t)b * HIDCH + c) * WIDTH + w0 + t8;
    *(uint4*)(g_rh + obase) = *(uint4*)o16;
}

// ============================================================
// HMMA fp16 2-term GEMM, 3-stage cp.async pipeline
//   MODE 0: C = x@Wv + bv  -> fp16 g_vh
//   MODE 1: C = r@Wo + bo  -> fp32 Out
// ============================================================
#define SA_STRIDE 80     // bytes per A row (32 fp16 + 16B pad)
#define SB_STRIDE 272    // bytes per B k-row (128 fp16 + 16B pad)
#define OFF_AHI 0
#define OFF_ALO 10240
#define OFF_B   20480
#define STG_SZ  29184    // 20480 + 32*272
#define SM_STG  1024
#define SM_TOT_MMA (SM_STG + 3 * STG_SZ)   // 88576

template <int MODE>
__global__ void __launch_bounds__(256, 2)
gemm_mma(const float* __restrict__ bias, float* __restrict__ Out) {
    extern __shared__ __align__(16) char smem[];
    const uint32_t sbu = smem_to_u32(smem);
    float* sbias = (float*)smem;

    const int tid  = threadIdx.x;
    const int wid  = tid >> 5;
    const int lane = tid & 31;
    const int warp_m = wid >> 2;
    const int warp_n = wid & 3;
    const int bn = blockIdx.x * 128;   // w base
    const int cm = blockIdx.y * 128;   // c base
    const int b  = blockIdx.z;

    const __half* Whi = (MODE == 0) ? g_wvhi : g_wohi;
    const __half* Wlo = (MODE == 0) ? g_wvlo : g_wolo;
    const __half* Xh  = ((MODE == 0) ? g_xh : g_rh) + (size_t)b * CINCH * WIDTH;

    if (tid < 128) sbias[tid] = bias[cm + tid];

    const int av0 = tid * 2;
    auto issue = [&](int chunk, int slot) {
        const uint32_t stgu = sbu + SM_STG + slot * STG_SZ;
        const int k0 = chunk * 32;
        #pragma unroll
        for (int j = 0; j < 2; j++) {
            int v = av0 + j;
            int r = v >> 2, c4 = v & 3;
            const __half* sh = Whi + (size_t)(cm + r) * CINCH + k0 + c4 * 8;
            const __half* sl = Wlo + (size_t)(cm + r) * CINCH + k0 + c4 * 8;
            cp_async16(stgu + OFF_AHI + r * SA_STRIDE + c4 * 16, sh);
            cp_async16(stgu + OFF_ALO + r * SA_STRIDE + c4 * 16, sl);
        }
        #pragma unroll
        for (int j = 0; j < 2; j++) {
            int v = av0 + j;
            int r = v >> 4, c = v & 15;
            const __half* sx = Xh + (size_t)(k0 + r) * WIDTH + bn + c * 8;
            cp_async16(stgu + OFF_B + r * SB_STRIDE + c * 16, sx);
        }
        CP_COMMIT();
    };

    float d[4][4][4];
    #pragma unroll
    for (int mi = 0; mi < 4; mi++)
        #pragma unroll
        for (int ni = 0; ni < 4; ni++)
            #pragma unroll
            for (int e = 0; e < 4; e++) d[mi][ni][e] = 0.f;

    issue(0, 0);
    issue(1, 1);

    for (int i = 0; i < 8; i++) {
        CP_WAIT(1);
        __syncthreads();
        if (i < 6) issue(i + 2, (i + 2) % 3);

        const uint32_t stgb = sbu + SM_STG + (i % 3) * STG_SZ;
        #pragma unroll
        for (int ks = 0; ks < 2; ks++) {
            uint32_t ah[4][4], al[4][4];
            #pragma unroll
            for (int mi = 0; mi < 4; mi++) {
                uint32_t addr = stgb + OFF_AHI
                    + (uint32_t)(warp_m * 64 + mi * 16 + (lane & 15)) * SA_STRIDE
                    + ks * 32 + (lane >> 4) * 16;
                ldsm_x4(ah[mi], addr);
                ldsm_x4(al[mi], addr + (OFF_ALO - OFF_AHI));
            }
            #pragma unroll
            for (int ni = 0; ni < 4; ni++) {
                uint32_t addr = stgb + OFF_B
                    + (uint32_t)(ks * 16 + (lane & 15)) * SB_STRIDE
                    + (warp_n * 32 + ni * 8) * 2;
                uint32_t bh[2];
                ldsm_x2t(bh, addr);
                #pragma unroll
                for (int mi = 0; mi < 4; mi++) mma_f16(d[mi][ni], ah[mi], bh);
                #pragma unroll
                for (int mi = 0; mi < 4; mi++) mma_f16(d[mi][ni], al[mi], bh);
            }
        }
    }

    // ---- epilogue ----
    #pragma unroll
    for (int mi = 0; mi < 4; mi++) {
        int cl0 = warp_m * 64 + mi * 16 + (lane >> 2);
        int c0 = cm + cl0;
        float bv0 = sbias[cl0];
        float bv1 = sbias[cl0 + 8];
        #pragma unroll
        for (int ni = 0; ni < 4; ni++) {
            int w0 = bn + warp_n * 32 + ni * 8 + (lane & 3) * 2;
            if (MODE == 0) {
                __half2 p0, p1;
                p0.x = __float2half_rn(d[mi][ni][0] + bv0);
                p0.y = __float2half_rn(d[mi][ni][1] + bv0);
                p1.x = __float2half_rn(d[mi][ni][2] + bv1);
                p1.y = __float2half_rn(d[mi][ni][3] + bv1);
                *(__half2*)&g_vh[((size_t)b * HIDCH + c0) * WIDTH + w0]     = p0;
                *(__half2*)&g_vh[((size_t)b * HIDCH + c0 + 8) * WIDTH + w0] = p1;
            } else {
                float2 o0, o1;
                o0.x = d[mi][ni][0] + bv0;
                o0.y = d[mi][ni][1] + bv0;
                o1.x = d[mi][ni][2] + bv1;
                o1.y = d[mi][ni][3] + bv1;
                *(float2*)&Out[((size_t)b * HIDCH + c0) * WIDTH + w0]     = o0;
                *(float2*)&Out[((size_t)b * HIDCH + c0 + 8) * WIDTH + w0] = o1;
            }
        }
    }
}

// ============================================================
extern "C" void kernel_launch(void* const* d_in, const int* in_sizes, int n_in,
                              void* d_out, int out_size) {
    const float* x     = (const float*)d_in[0];
    const float* query = (const float*)d_in[1];
    const float* Wk    = (const float*)d_in[2];
    const float* Wkb   = (const float*)d_in[3];
    const float* rpe   = (const float*)d_in[4];
    const float* Wv    = (const float*)d_in[5];
    const float* bv    = (const float*)d_in[6];
    const float* Wo    = (const float*)d_in[7];
    const float* bo    = (const float*)d_in[8];
    float* out = (float*)d_out;

    cudaFuncSetAttribute(gemm_mma<0>, cudaFuncAttributeMaxDynamicSharedMemorySize, SM_TOT_MMA);
    cudaFuncSetAttribute(gemm_mma<1>, cudaFuncAttributeMaxDynamicSharedMemorySize, SM_TOT_MMA);

    precompute_kernel<<<1, 256>>>(query, Wk, Wkb);
    {
        __half *dvh, *dvl, *doh, *dol;
        cudaGetSymbolAddress((void**)&dvh, g_wvhi);
        cudaGetSymbolAddress((void**)&dvl, g_wvlo);
        cudaGetSymbolAddress((void**)&doh, g_wohi);
        cudaGetSymbolAddress((void**)&dol, g_wolo);
        wsplit_kernel<<<32, 256>>>(Wv, dvh, dvl);
        wsplit_kernel<<<32, 256>>>(Wo, doh, dol);
    }
    xsplit_cost_kernel<<<dim3(WIDTH / 256, BATCH), 256>>>(x);
    denom_kernel<<<dim3(WIDTH / 256, NHEADS, BATCH), 256>>>(rpe);
    gemm_mma<0><<<dim3(WIDTH / 128, HIDCH / 128, BATCH), 256, SM_TOT_MMA>>>(bv, nullptr);
    conv_kernel<<<dim3(WIDTH / CTILE, HIDCH, BATCH), 256>>>(rpe);
    gemm_mma<1><<<dim3(WIDTH / 128, HIDCH / 128, BATCH), 256, SM_TOT_MMA>>>(bo, out);
}